// round 3
// baseline (speedup 1.0000x reference)
#include <cuda_runtime.h>
#include <math.h>
#include <stdint.h>

#define EDIM 1024
#define TSEQ 2048
#define NTOK 4096      // B * T
#define FFD  4096
#define HDIM 64
#define LN_EPS 1e-5f

// ---------------- scratch (static device globals; no allocation) ----------------
__device__ float g_h [(size_t)NTOK*EDIM];
__device__ float g_q [(size_t)NTOK*EDIM];
__device__ float g_kb[(size_t)NTOK*EDIM];
__device__ float g_vb[(size_t)NTOK*EDIM];
__device__ float g_ao[(size_t)NTOK*EDIM];
__device__ float g_x1[(size_t)NTOK*EDIM];
__device__ float g_x2[(size_t)NTOK*EDIM];
__device__ float g_ff[(size_t)NTOK*FFD];

// ---------------- tf32 helpers ----------------
__device__ __forceinline__ float tf32r(float x){
    uint32_t u; asm("cvt.rna.tf32.f32 %0, %1;" : "=r"(u) : "f"(x));
    return __uint_as_float(u);
}
__device__ __forceinline__ uint32_t tf32u(float x){
    uint32_t u; asm("cvt.rna.tf32.f32 %0, %1;" : "=r"(u) : "f"(x));
    return u;
}
__device__ __forceinline__ void mma_tf32(float* c, const uint32_t* a, uint32_t b0, uint32_t b1){
    asm volatile("mma.sync.aligned.m16n8k8.row.col.f32.tf32.tf32.f32 "
        "{%0,%1,%2,%3}, {%4,%5,%6,%7}, {%8,%9}, {%0,%1,%2,%3};"
        : "+f"(c[0]), "+f"(c[1]), "+f"(c[2]), "+f"(c[3])
        : "r"(a[0]), "r"(a[1]), "r"(a[2]), "r"(a[3]), "r"(b0), "r"(b1));
}

// ---------------- LayerNorm: one block per row of 1024 ----------------
__global__ __launch_bounds__(256)
void ln_kernel(const float* __restrict__ x, const float* __restrict__ gamma,
               const float* __restrict__ beta, float* __restrict__ out)
{
    const int row = blockIdx.x;
    const int t = threadIdx.x;
    const float4 v = ((const float4*)(x + (size_t)row*EDIM))[t];
    float s  = v.x + v.y + v.z + v.w;
    float ss = v.x*v.x + v.y*v.y + v.z*v.z + v.w*v.w;
#pragma unroll
    for (int o = 16; o; o >>= 1){
        s  += __shfl_xor_sync(0xffffffffu, s,  o);
        ss += __shfl_xor_sync(0xffffffffu, ss, o);
    }
    __shared__ float sh_s[8], sh_ss[8];
    const int w = t >> 5, l = t & 31;
    if (l == 0){ sh_s[w] = s; sh_ss[w] = ss; }
    __syncthreads();
    if (w == 0){
        s  = (l < 8) ? sh_s[l]  : 0.f;
        ss = (l < 8) ? sh_ss[l] : 0.f;
#pragma unroll
        for (int o = 4; o; o >>= 1){
            s  += __shfl_xor_sync(0xffffffffu, s,  o);
            ss += __shfl_xor_sync(0xffffffffu, ss, o);
        }
        if (l == 0){ sh_s[0] = s; sh_ss[0] = ss; }
    }
    __syncthreads();
    const float mu   = sh_s[0] * (1.f/EDIM);
    const float var  = sh_ss[0] * (1.f/EDIM) - mu*mu;
    const float rstd = rsqrtf(var + LN_EPS);
    const float4 g4 = ((const float4*)gamma)[t];
    const float4 b4 = ((const float4*)beta)[t];
    float4 o4;
    o4.x = (v.x - mu)*rstd*g4.x + b4.x;
    o4.y = (v.y - mu)*rstd*g4.y + b4.y;
    o4.z = (v.z - mu)*rstd*g4.z + b4.z;
    o4.w = (v.w - mu)*rstd*g4.w + b4.w;
    ((float4*)(out + (size_t)row*EDIM))[t] = o4;
}

// ---------------- TF32 GEMM: C[M,N] = A[M,K] @ W[K,N] + bias (+res)(+relu) ----
// 128x128 block tile, BK=16 double-buffered, 256 thr = 8 warps (4m x 2n),
// warp tile 32x64 = 2 m-atoms x 8 n-atoms of mma.m16n8k8.tf32.
template<bool RELU, bool RES>
__global__ __launch_bounds__(256)
void gemm_tf32(const float* __restrict__ A, const float* __restrict__ W,
               const float* __restrict__ bias, const float* __restrict__ res,
               float* __restrict__ C, int N, int K)
{
    __shared__ float As[2][128][20];    // [m][k], stride 20 -> conflict-free frags
    __shared__ float Bs[2][16][136];    // [k][n], stride 136 -> conflict-free frags

    const int tid  = threadIdx.x;
    const int lane = tid & 31;
    const int wid  = tid >> 5;
    const int gid  = lane >> 2;      // 0..7
    const int tig  = lane & 3;       // 0..3
    const int wm   = (wid & 3) * 32; // warp row base in tile
    const int wn   = (wid >> 2) * 64;// warp col base in tile
    const int m0 = blockIdx.y * 128;
    const int n0 = blockIdx.x * 128;

    // gmem->smem mapping (2 float4 of A, 2 float4 of B per thread per stage)
    const int a_row = tid >> 2;          // 0..63 (and +64)
    const int a_col = (tid & 3) * 4;     // 0,4,8,12
    const int b_row = tid >> 5;          // 0..7 (and +8)
    const int b_col = (tid & 31) * 4;    // 0..124
    const float* Ap0 = A + (size_t)(m0 + a_row)*K + a_col;
    const float* Ap1 = A + (size_t)(m0 + a_row + 64)*K + a_col;
    const float* Wp0 = W + (size_t)b_row*N + n0 + b_col;
    const float* Wp1 = W + (size_t)(b_row + 8)*N + n0 + b_col;

    float acc[2][8][4];
#pragma unroll
    for (int i = 0; i < 2; i++)
#pragma unroll
        for (int j = 0; j < 8; j++)
#pragma unroll
            for (int k = 0; k < 4; k++) acc[i][j][k] = 0.f;

    // prologue: fill stage 0
    {
        float4 a0 = *(const float4*)Ap0;
        float4 a1 = *(const float4*)Ap1;
        float4 b0 = *(const float4*)Wp0;
        float4 b1 = *(const float4*)Wp1;
        float4 t;
        t.x=tf32r(a0.x); t.y=tf32r(a0.y); t.z=tf32r(a0.z); t.w=tf32r(a0.w);
        *(float4*)&As[0][a_row][a_col] = t;
        t.x=tf32r(a1.x); t.y=tf32r(a1.y); t.z=tf32r(a1.z); t.w=tf32r(a1.w);
        *(float4*)&As[0][a_row+64][a_col] = t;
        t.x=tf32r(b0.x); t.y=tf32r(b0.y); t.z=tf32r(b0.z); t.w=tf32r(b0.w);
        *(float4*)&Bs[0][b_row][b_col] = t;
        t.x=tf32r(b1.x); t.y=tf32r(b1.y); t.z=tf32r(b1.z); t.w=tf32r(b1.w);
        *(float4*)&Bs[0][b_row+8][b_col] = t;
    }

    const int KT = K >> 4;
    for (int kt = 0; kt < KT; ++kt){
        __syncthreads();
        const int buf = kt & 1;
        float4 na0, na1, nb0, nb1;
        const bool more = (kt + 1 < KT);
        if (more){
            const int ko = (kt + 1) * 16;
            na0 = *(const float4*)(Ap0 + ko);
            na1 = *(const float4*)(Ap1 + ko);
            nb0 = *(const float4*)(Wp0 + (size_t)ko*N);
            nb1 = *(const float4*)(Wp1 + (size_t)ko*N);
        }
#pragma unroll
        for (int kk = 0; kk < 16; kk += 8){
            uint32_t afr[2][4];
#pragma unroll
            for (int ma = 0; ma < 2; ma++){
                const int r = wm + ma*16 + gid;
                afr[ma][0] = __float_as_uint(As[buf][r    ][kk + tig]);
                afr[ma][1] = __float_as_uint(As[buf][r + 8][kk + tig]);
                afr[ma][2] = __float_as_uint(As[buf][r    ][kk + tig + 4]);
                afr[ma][3] = __float_as_uint(As[buf][r + 8][kk + tig + 4]);
            }
#pragma unroll
            for (int na = 0; na < 8; na++){
                const int c = wn + na*8 + gid;
                const uint32_t b0 = __float_as_uint(Bs[buf][kk + tig    ][c]);
                const uint32_t b1 = __float_as_uint(Bs[buf][kk + tig + 4][c]);
                mma_tf32(acc[0][na], afr[0], b0, b1);
                mma_tf32(acc[1][na], afr[1], b0, b1);
            }
        }
        if (more){
            const int nxt = buf ^ 1;
            float4 t;
            t.x=tf32r(na0.x); t.y=tf32r(na0.y); t.z=tf32r(na0.z); t.w=tf32r(na0.w);
            *(float4*)&As[nxt][a_row][a_col] = t;
            t.x=tf32r(na1.x); t.y=tf32r(na1.y); t.z=tf32r(na1.z); t.w=tf32r(na1.w);
            *(float4*)&As[nxt][a_row+64][a_col] = t;
            t.x=tf32r(nb0.x); t.y=tf32r(nb0.y); t.z=tf32r(nb0.z); t.w=tf32r(nb0.w);
            *(float4*)&Bs[nxt][b_row][b_col] = t;
            t.x=tf32r(nb1.x); t.y=tf32r(nb1.y); t.z=tf32r(nb1.z); t.w=tf32r(nb1.w);
            *(float4*)&Bs[nxt][b_row+8][b_col] = t;
        }
    }

    // epilogue: accum layout c0,c1 -> row r, cols 2*tig,2*tig+1; c2,c3 -> row r+8
#pragma unroll
    for (int ma = 0; ma < 2; ma++){
        const int r0 = m0 + wm + ma*16 + gid;
        const int r1 = r0 + 8;
#pragma unroll
        for (int na = 0; na < 8; na++){
            const int c = n0 + wn + na*8 + 2*tig;
            const float2 bb = *(const float2*)&bias[c];
            float v00 = acc[ma][na][0] + bb.x;
            float v01 = acc[ma][na][1] + bb.y;
            float v10 = acc[ma][na][2] + bb.x;
            float v11 = acc[ma][na][3] + bb.y;
            if (RELU){
                v00 = fmaxf(v00, 0.f); v01 = fmaxf(v01, 0.f);
                v10 = fmaxf(v10, 0.f); v11 = fmaxf(v11, 0.f);
            }
            if (RES){
                const float2 r0v = *(const float2*)&res[(size_t)r0*N + c];
                const float2 r1v = *(const float2*)&res[(size_t)r1*N + c];
                v00 += r0v.x; v01 += r0v.y; v10 += r1v.x; v11 += r1v.y;
            }
            float2 o0; o0.x = v00; o0.y = v01;
            float2 o1; o1.x = v10; o1.y = v11;
            *(float2*)&C[(size_t)r0*N + c] = o0;
            *(float2*)&C[(size_t)r1*N + c] = o1;
        }
    }
}

// ---------------- Flash attention, TF32 mma + fp32 online softmax ----------------
// Block = 64 queries x 64 head dims for one (b,h); key tiles of 64.
// 8 warps (4m x 2n): warp tile S = 16x32 (4 n-atoms), O = 16x32 dims.
template<bool CAUSAL>
__global__ __launch_bounds__(256)
void attn_tf32(const float* __restrict__ Qg, const float* __restrict__ Kg,
               const float* __restrict__ Vg, float* __restrict__ Og)
{
    const int AP = 76;                   // row stride: conflict-free for all frags
    extern __shared__ float sm[];
    float* Qs   = sm;                    // [64][76] tf32
    float* Ks   = Qs + 64*AP;            // [64][76] tf32
    float* Vs   = Ks + 64*AP;            // [64][76] tf32
    float* Ss   = Vs + 64*AP;            // [64][76] fp32 scores / probs
    float* mrow = Ss + 64*AP;
    float* lrow = mrow + 64;
    float* arow = lrow + 64;

    const int tid  = threadIdx.x;
    const int lane = tid & 31;
    const int wid  = tid >> 5;
    const int gid  = lane >> 2;
    const int tig  = lane & 3;
    const int wm   = (wid & 3) * 16;     // 4 m-warps x 16 rows
    const int wn   = (wid >> 2) * 32;    // 2 n-warps x 32 cols
    const int qt = blockIdx.x, h = blockIdx.y, b = blockIdx.z;
    const size_t base = (size_t)b*TSEQ*EDIM + (size_t)h*HDIM;

    // load Q tile (convert to tf32 once)
#pragma unroll
    for (int i = 0; i < 4; i++){
        const int t4 = tid + i*256;
        const int r = t4 >> 4;
        const int c = (t4 & 15) << 2;
        const float4 v = *(const float4*)&Qg[base + (size_t)(qt*64 + r)*EDIM + c];
        Qs[r*AP + c + 0] = tf32r(v.x);
        Qs[r*AP + c + 1] = tf32r(v.y);
        Qs[r*AP + c + 2] = tf32r(v.z);
        Qs[r*AP + c + 3] = tf32r(v.w);
    }
    if (tid < 64){ mrow[tid] = -1e30f; lrow[tid] = 0.f; }

    float oacc[4][4];
#pragma unroll
    for (int i = 0; i < 4; i++)
#pragma unroll
        for (int j = 0; j < 4; j++) oacc[i][j] = 0.f;

    const int nkt = CAUSAL ? (qt + 1) : (TSEQ/64);

    for (int kt = 0; kt < nkt; ++kt){
        __syncthreads();
#pragma unroll
        for (int i = 0; i < 4; i++){
            const int t4 = tid + i*256;
            const int r = t4 >> 4;
            const int c = (t4 & 15) << 2;
            const size_t go = base + (size_t)(kt*64 + r)*EDIM + c;
            const float4 kv = *(const float4*)&Kg[go];
            const float4 vv = *(const float4*)&Vg[go];
            Ks[r*AP + c + 0] = tf32r(kv.x);
            Ks[r*AP + c + 1] = tf32r(kv.y);
            Ks[r*AP + c + 2] = tf32r(kv.z);
            Ks[r*AP + c + 3] = tf32r(kv.w);
            Vs[r*AP + c + 0] = tf32r(vv.x);
            Vs[r*AP + c + 1] = tf32r(vv.y);
            Vs[r*AP + c + 2] = tf32r(vv.z);
            Vs[r*AP + c + 3] = tf32r(vv.w);
        }
        __syncthreads();

        // ---- S = Q K^T (warp: 16x32 via 4 n-atoms, K over d in 8-chunks) ----
        float sa[4][4];
#pragma unroll
        for (int na = 0; na < 4; na++)
#pragma unroll
            for (int k = 0; k < 4; k++) sa[na][k] = 0.f;
#pragma unroll
        for (int d8 = 0; d8 < 8; d8++){
            const int d = d8 * 8;
            uint32_t afr[4];
            afr[0] = __float_as_uint(Qs[(wm + gid    )*AP + d + tig]);
            afr[1] = __float_as_uint(Qs[(wm + gid + 8)*AP + d + tig]);
            afr[2] = __float_as_uint(Qs[(wm + gid    )*AP + d + tig + 4]);
            afr[3] = __float_as_uint(Qs[(wm + gid + 8)*AP + d + tig + 4]);
#pragma unroll
            for (int na = 0; na < 4; na++){
                const int kr = wn + na*8 + gid;
                const uint32_t b0 = __float_as_uint(Ks[kr*AP + d + tig]);
                const uint32_t b1 = __float_as_uint(Ks[kr*AP + d + tig + 4]);
                mma_tf32(sa[na], afr, b0, b1);
            }
        }
        // scale + causal mask + store to Ss
        {
            const int r0 = wm + gid;
            const int r1 = r0 + 8;
            const int gr0 = qt*64 + r0;
            const int gr1 = qt*64 + r1;
#pragma unroll
            for (int na = 0; na < 4; na++){
                const int col = wn + na*8 + 2*tig;
                const int gc  = kt*64 + col;
                float v00 = sa[na][0] * 0.125f;
                float v01 = sa[na][1] * 0.125f;
                float v10 = sa[na][2] * 0.125f;
                float v11 = sa[na][3] * 0.125f;
                if (CAUSAL){
                    if (gc     > gr0) v00 = -1e30f;
                    if (gc + 1 > gr0) v01 = -1e30f;
                    if (gc     > gr1) v10 = -1e30f;
                    if (gc + 1 > gr1) v11 = -1e30f;
                }
                float2 s0; s0.x = v00; s0.y = v01;
                float2 s1; s1.x = v10; s1.y = v11;
                *(float2*)&Ss[r0*AP + col] = s0;
                *(float2*)&Ss[r1*AP + col] = s1;
            }
        }
        __syncthreads();

        // ---- online softmax: 4 lanes per row, 16 cols each ----
        {
            const int r = tid >> 2;
            const int g = tid & 3;
            float* srow = &Ss[r*AP + g*16];
            const float mold = mrow[r];
            float mx = -1e30f;
#pragma unroll
            for (int c = 0; c < 16; c++) mx = fmaxf(mx, srow[c]);
            mx = fmaxf(mx, __shfl_xor_sync(0xffffffffu, mx, 1));
            mx = fmaxf(mx, __shfl_xor_sync(0xffffffffu, mx, 2));
            const float mnew = fmaxf(mold, mx);
            float sum = 0.f;
#pragma unroll
            for (int c = 0; c < 16; c++){
                const float p = __expf(srow[c] - mnew);
                srow[c] = p;
                sum += p;
            }
            sum += __shfl_xor_sync(0xffffffffu, sum, 1);
            sum += __shfl_xor_sync(0xffffffffu, sum, 2);
            if (g == 0){
                const float al = __expf(mold - mnew);
                mrow[r] = mnew;
                lrow[r] = lrow[r]*al + sum;
                arow[r] = al;
            }
        }
        __syncthreads();

        // ---- O = O*alpha + P @ V ----
        const float al0 = arow[wm + gid];
        const float al1 = arow[wm + gid + 8];
#pragma unroll
        for (int na = 0; na < 4; na++){
            oacc[na][0] *= al0; oacc[na][1] *= al0;
            oacc[na][2] *= al1; oacc[na][3] *= al1;
        }
#pragma unroll
        for (int k8 = 0; k8 < 8; k8++){
            const int kk = k8 * 8;
            uint32_t afr[4];
            afr[0] = tf32u(Ss[(wm + gid    )*AP + kk + tig]);
            afr[1] = tf32u(Ss[(wm + gid + 8)*AP + kk + tig]);
            afr[2] = tf32u(Ss[(wm + gid    )*AP + kk + tig + 4]);
            afr[3] = tf32u(Ss[(wm + gid + 8)*AP + kk + tig + 4]);
#pragma unroll
            for (int na = 0; na < 4; na++){
                const int dc = wn + na*8 + gid;
                const uint32_t b0 = __float_as_uint(Vs[(kk + tig    )*AP + dc]);
                const uint32_t b1 = __float_as_uint(Vs[(kk + tig + 4)*AP + dc]);
                mma_tf32(oacc[na], afr, b0, b1);
            }
        }
    }

    // normalize + write (float2 per row pair)
    const float li0 = 1.f / lrow[wm + gid];
    const float li1 = 1.f / lrow[wm + gid + 8];
    const int row0 = qt*64 + wm + gid;
    const int row1 = row0 + 8;
#pragma unroll
    for (int na = 0; na < 4; na++){
        const int col = wn + na*8 + 2*tig;
        float2 o0; o0.x = oacc[na][0]*li0; o0.y = oacc[na][1]*li0;
        float2 o1; o1.x = oacc[na][2]*li1; o1.y = oacc[na][3]*li1;
        *(float2*)&Og[base + (size_t)row0*EDIM + col] = o0;
        *(float2*)&Og[base + (size_t)row1*EDIM + col] = o1;
    }
}

// ---------------- launch ----------------
extern "C" void kernel_launch(void* const* d_in, const int* in_sizes, int n_in,
                              void* d_out, int out_size)
{
    const float* x     = (const float*)d_in[0];
    const float* enc   = (const float*)d_in[1];
    // d_in[2] = tgt_mask: deterministic causal tril, applied analytically
    const float* sa_wq = (const float*)d_in[3];  const float* sa_bq = (const float*)d_in[4];
    const float* sa_wk = (const float*)d_in[5];  const float* sa_bk = (const float*)d_in[6];
    const float* sa_wv = (const float*)d_in[7];  const float* sa_bv = (const float*)d_in[8];
    const float* sa_wo = (const float*)d_in[9];  const float* sa_bo = (const float*)d_in[10];
    const float* ca_wq = (const float*)d_in[11]; const float* ca_bq = (const float*)d_in[12];
    const float* ca_wk = (const float*)d_in[13]; const float* ca_bk = (const float*)d_in[14];
    const float* ca_wv = (const float*)d_in[15]; const float* ca_bv = (const float*)d_in[16];
    const float* ca_wo = (const float*)d_in[17]; const float* ca_bo = (const float*)d_in[18];
    const float* ff_w1 = (const float*)d_in[19]; const float* ff_b1 = (const float*)d_in[20];
    const float* ff_w2 = (const float*)d_in[21]; const float* ff_b2 = (const float*)d_in[22];
    const float* ln1g  = (const float*)d_in[23]; const float* ln1b  = (const float*)d_in[24];
    const float* ln2g  = (const float*)d_in[25]; const float* ln2b  = (const float*)d_in[26];
    const float* ln3g  = (const float*)d_in[27]; const float* ln3b  = (const float*)d_in[28];
    float* out = (float*)d_out;

    float *h, *q, *k, *v, *ao, *x1, *x2, *ff;
    cudaGetSymbolAddress((void**)&h,  g_h);
    cudaGetSymbolAddress((void**)&q,  g_q);
    cudaGetSymbolAddress((void**)&k,  g_kb);
    cudaGetSymbolAddress((void**)&v,  g_vb);
    cudaGetSymbolAddress((void**)&ao, g_ao);
    cudaGetSymbolAddress((void**)&x1, g_x1);
    cudaGetSymbolAddress((void**)&x2, g_x2);
    cudaGetSymbolAddress((void**)&ff, g_ff);

    const int ATTN_SMEM = (4*64*76 + 3*64) * (int)sizeof(float);   // 78592 B
    cudaFuncSetAttribute(attn_tf32<true>,  cudaFuncAttributeMaxDynamicSharedMemorySize, ATTN_SMEM);
    cudaFuncSetAttribute(attn_tf32<false>, cudaFuncAttributeMaxDynamicSharedMemorySize, ATTN_SMEM);

    const dim3 thr(256);
    const dim3 gP (EDIM/128, NTOK/128);    // 8 x 32
    const dim3 gF1(FFD/128,  NTOK/128);    // 32 x 32
    const dim3 gA (TSEQ/64, 16, 2);        // 32 x 16 x 2

    // ---- self attention block ----
    ln_kernel<<<NTOK, 256>>>(x, ln1g, ln1b, h);
    gemm_tf32<false,false><<<gP, thr>>>(h, sa_wq, sa_bq, nullptr, q, EDIM, EDIM);
    gemm_tf32<false,false><<<gP, thr>>>(h, sa_wk, sa_bk, nullptr, k, EDIM, EDIM);
    gemm_tf32<false,false><<<gP, thr>>>(h, sa_wv, sa_bv, nullptr, v, EDIM, EDIM);
    attn_tf32<true><<<gA, thr, ATTN_SMEM>>>(q, k, v, ao);
    gemm_tf32<false,true ><<<gP, thr>>>(ao, sa_wo, sa_bo, x, x1, EDIM, EDIM);

    // ---- cross attention block ----
    ln_kernel<<<NTOK, 256>>>(x1, ln2g, ln2b, h);
    gemm_tf32<false,false><<<gP, thr>>>(h,   ca_wq, ca_bq, nullptr, q, EDIM, EDIM);
    gemm_tf32<false,false><<<gP, thr>>>(enc, ca_wk, ca_bk, nullptr, k, EDIM, EDIM);
    gemm_tf32<false,false><<<gP, thr>>>(enc, ca_wv, ca_bv, nullptr, v, EDIM, EDIM);
    attn_tf32<false><<<gA, thr, ATTN_SMEM>>>(q, k, v, ao);
    gemm_tf32<false,true ><<<gP, thr>>>(ao, ca_wo, ca_bo, x1, x2, EDIM, EDIM);

    // ---- feed-forward block ----
    ln_kernel<<<NTOK, 256>>>(x2, ln3g, ln3b, h);
    gemm_tf32<true ,false><<<gF1, thr>>>(h,  ff_w1, ff_b1, nullptr, ff, FFD, EDIM);
    gemm_tf32<false,true ><<<gP, thr>>>(ff, ff_w2, ff_b2, x2, out, EDIM, FFD);
}

// round 4
// speedup vs baseline: 1.7901x; 1.7901x over previous
#include <cuda_runtime.h>
#include <cuda_fp16.h>
#include <math.h>
#include <stdint.h>

#define EDIM 1024
#define TSEQ 2048
#define NTOK 4096
#define FFD  4096
#define HDIM 64
#define LN_EPS 1e-5f

__device__ float g_h [(size_t)NTOK*EDIM];
__device__ float g_q [(size_t)NTOK*EDIM];
__device__ float g_kb[(size_t)NTOK*EDIM];
__device__ float g_vb[(size_t)NTOK*EDIM];
__device__ float g_ao[(size_t)NTOK*EDIM];
__device__ float g_x1[(size_t)NTOK*EDIM];
__device__ float g_x2[(size_t)NTOK*EDIM];
__device__ float g_ff[(size_t)NTOK*FFD];

// ---------------- helpers ----------------
__device__ __forceinline__ float tf32r(float x){
    uint32_t u; asm("cvt.rna.tf32.f32 %0, %1;" : "=r"(u) : "f"(x));
    return __uint_as_float(u);
}
__device__ __forceinline__ uint32_t tf32u(float x){
    uint32_t u; asm("cvt.rna.tf32.f32 %0, %1;" : "=r"(u) : "f"(x));
    return u;
}
__device__ __forceinline__ void mma_tf32(float* c, const uint32_t* a, uint32_t b0, uint32_t b1){
    asm volatile("mma.sync.aligned.m16n8k8.row.col.f32.tf32.tf32.f32 "
        "{%0,%1,%2,%3}, {%4,%5,%6,%7}, {%8,%9}, {%0,%1,%2,%3};"
        : "+f"(c[0]), "+f"(c[1]), "+f"(c[2]), "+f"(c[3])
        : "r"(a[0]), "r"(a[1]), "r"(a[2]), "r"(a[3]), "r"(b0), "r"(b1));
}
__device__ __forceinline__ uint32_t h2pack(float lo, float hi){
    __half2 h = __floats2half2_rn(lo, hi);
    return *(uint32_t*)&h;
}
__device__ __forceinline__ void mma_f16(float* c, const uint32_t* a, uint32_t b0, uint32_t b1){
    asm volatile("mma.sync.aligned.m16n8k16.row.col.f32.f16.f16.f32 "
        "{%0,%1,%2,%3}, {%4,%5,%6,%7}, {%8,%9}, {%0,%1,%2,%3};"
        : "+f"(c[0]), "+f"(c[1]), "+f"(c[2]), "+f"(c[3])
        : "r"(a[0]), "r"(a[1]), "r"(a[2]), "r"(a[3]), "r"(b0), "r"(b1));
}
// B smem word index: n-major, 20-word rows, kp (0..15) xor-swizzled by n>>3
__device__ __forceinline__ int bofs(int n, int kp){
    return n*20 + (kp ^ ((n>>3)&15));
}

// ---------------- LayerNorm ----------------
__global__ __launch_bounds__(256)
void ln_kernel(const float* __restrict__ x, const float* __restrict__ gamma,
               const float* __restrict__ beta, float* __restrict__ out)
{
    const int row = blockIdx.x;
    const int t = threadIdx.x;
    const float4 v = ((const float4*)(x + (size_t)row*EDIM))[t];
    float s  = v.x + v.y + v.z + v.w;
    float ss = v.x*v.x + v.y*v.y + v.z*v.z + v.w*v.w;
#pragma unroll
    for (int o = 16; o; o >>= 1){
        s  += __shfl_xor_sync(0xffffffffu, s,  o);
        ss += __shfl_xor_sync(0xffffffffu, ss, o);
    }
    __shared__ float sh_s[8], sh_ss[8];
    const int w = t >> 5, l = t & 31;
    if (l == 0){ sh_s[w] = s; sh_ss[w] = ss; }
    __syncthreads();
    if (w == 0){
        s  = (l < 8) ? sh_s[l]  : 0.f;
        ss = (l < 8) ? sh_ss[l] : 0.f;
#pragma unroll
        for (int o = 4; o; o >>= 1){
            s  += __shfl_xor_sync(0xffffffffu, s,  o);
            ss += __shfl_xor_sync(0xffffffffu, ss, o);
        }
        if (l == 0){ sh_s[0] = s; sh_ss[0] = ss; }
    }
    __syncthreads();
    const float mu   = sh_s[0] * (1.f/EDIM);
    const float var  = sh_ss[0] * (1.f/EDIM) - mu*mu;
    const float rstd = rsqrtf(var + LN_EPS);
    const float4 g4 = ((const float4*)gamma)[t];
    const float4 b4 = ((const float4*)beta)[t];
    float4 o4;
    o4.x = (v.x - mu)*rstd*g4.x + b4.x;
    o4.y = (v.y - mu)*rstd*g4.y + b4.y;
    o4.z = (v.z - mu)*rstd*g4.z + b4.z;
    o4.w = (v.w - mu)*rstd*g4.w + b4.w;
    ((float4*)(out + (size_t)row*EDIM))[t] = o4;
}

// ---------------- FP16 GEMM: C = A@W + bias (+res)(+relu), f32 accum ----------
// 128x128 tile, BK=32 double-buffered, 8 warps (4m x 2n), warp 32x64,
// mma.m16n8k16: 2 m-atoms x 8 n-atoms, 2 k-chunks per stage.
template<bool RELU, bool RES>
__global__ __launch_bounds__(256)
void gemm_f16(const float* __restrict__ A, const float* __restrict__ W,
              const float* __restrict__ bias, const float* __restrict__ res,
              float* __restrict__ C, int N, int K)
{
    __shared__ uint32_t As[2][128*20];   // [m][k-pair], 16 used + 4 pad words
    __shared__ uint32_t Bs[2][128*20];   // n-major swizzled (bofs)

    const int tid  = threadIdx.x;
    const int lane = tid & 31;
    const int wid  = tid >> 5;
    const int gid  = lane >> 2;
    const int tig  = lane & 3;
    const int wm   = (wid & 3) * 32;
    const int wn   = (wid >> 2) * 64;
    const int m0 = blockIdx.y * 128;
    const int n0 = blockIdx.x * 128;

    const int a_row = tid >> 2;          // 0..63 (+64)
    const int a_k8  = (tid & 3) * 8;     // float index in BK=32
    const int b_kp  = tid >> 5;          // 0..7 (+8): k-pair row
    const int b_n4  = (tid & 31) * 4;

    const float* ApA = A + (size_t)(m0 + a_row)*K + a_k8;
    const float* ApB = A + (size_t)(m0 + a_row + 64)*K + a_k8;
    const float* Wp0 = W + (size_t)(2*b_kp)*N + n0 + b_n4;
    const float* Wp2 = W + (size_t)(2*(b_kp+8))*N + n0 + b_n4;

    float acc[2][8][4];
#pragma unroll
    for (int i = 0; i < 2; i++)
#pragma unroll
        for (int j = 0; j < 8; j++)
#pragma unroll
            for (int k = 0; k < 4; k++) acc[i][j][k] = 0.f;

    float4 ra0, ra1, ra2, ra3, rb0, rb1, rb2, rb3;

#define GLOAD(kt_) do{                                              \
        const size_t ko = (size_t)(kt_) * 32;                       \
        ra0 = *(const float4*)(ApA + ko);                           \
        ra1 = *(const float4*)(ApA + ko + 4);                       \
        ra2 = *(const float4*)(ApB + ko);                           \
        ra3 = *(const float4*)(ApB + ko + 4);                       \
        rb0 = *(const float4*)(Wp0 + ko*N);                         \
        rb1 = *(const float4*)(Wp0 + (ko+1)*N);                     \
        rb2 = *(const float4*)(Wp2 + ko*N);                         \
        rb3 = *(const float4*)(Wp2 + (ko+1)*N);                     \
    }while(0)

#define SSTORE(b_) do{                                              \
        uint4 pa;                                                   \
        pa.x = h2pack(ra0.x, ra0.y); pa.y = h2pack(ra0.z, ra0.w);   \
        pa.z = h2pack(ra1.x, ra1.y); pa.w = h2pack(ra1.z, ra1.w);   \
        *(uint4*)&As[b_][a_row*20 + (a_k8>>1)] = pa;                \
        pa.x = h2pack(ra2.x, ra2.y); pa.y = h2pack(ra2.z, ra2.w);   \
        pa.z = h2pack(ra3.x, ra3.y); pa.w = h2pack(ra3.z, ra3.w);   \
        *(uint4*)&As[b_][(a_row+64)*20 + (a_k8>>1)] = pa;           \
        float f0[4], f1[4], f2[4], f3[4];                           \
        *(float4*)f0 = rb0; *(float4*)f1 = rb1;                     \
        *(float4*)f2 = rb2; *(float4*)f3 = rb3;                     \
        _Pragma("unroll")                                           \
        for (int j = 0; j < 4; j++){                                \
            const int n = b_n4 + j;                                 \
            Bs[b_][bofs(n, b_kp)]   = h2pack(f0[j], f1[j]);         \
            Bs[b_][bofs(n, b_kp+8)] = h2pack(f2[j], f3[j]);         \
        }                                                           \
    }while(0)

    GLOAD(0);
    SSTORE(0);

    const int KT = K >> 5;
    for (int kt = 0; kt < KT; ++kt){
        __syncthreads();
        const int buf = kt & 1;
        const bool more = (kt + 1 < KT);
        if (more) GLOAD(kt + 1);
#pragma unroll
        for (int c = 0; c < 2; c++){
            const int kb = c * 8;
            uint32_t af[2][4];
#pragma unroll
            for (int ma = 0; ma < 2; ma++){
                const int r = wm + ma*16 + gid;
                af[ma][0] = As[buf][r*20     + kb + tig];
                af[ma][1] = As[buf][(r+8)*20 + kb + tig];
                af[ma][2] = As[buf][r*20     + kb + tig + 4];
                af[ma][3] = As[buf][(r+8)*20 + kb + tig + 4];
            }
#pragma unroll
            for (int na = 0; na < 8; na++){
                const int n = wn + na*8 + gid;
                const uint32_t b0 = Bs[buf][bofs(n, kb + tig)];
                const uint32_t b1 = Bs[buf][bofs(n, kb + tig + 4)];
                mma_f16(acc[0][na], af[0], b0, b1);
                mma_f16(acc[1][na], af[1], b0, b1);
            }
        }
        if (more) SSTORE(buf ^ 1);
    }
#undef GLOAD
#undef SSTORE

#pragma unroll
    for (int ma = 0; ma < 2; ma++){
        const int r0 = m0 + wm + ma*16 + gid;
        const int r1 = r0 + 8;
#pragma unroll
        for (int na = 0; na < 8; na++){
            const int c = n0 + wn + na*8 + 2*tig;
            const float2 bb = *(const float2*)&bias[c];
            float v00 = acc[ma][na][0] + bb.x;
            float v01 = acc[ma][na][1] + bb.y;
            float v10 = acc[ma][na][2] + bb.x;
            float v11 = acc[ma][na][3] + bb.y;
            if (RELU){
                v00 = fmaxf(v00, 0.f); v01 = fmaxf(v01, 0.f);
                v10 = fmaxf(v10, 0.f); v11 = fmaxf(v11, 0.f);
            }
            if (RES){
                const float2 r0v = *(const float2*)&res[(size_t)r0*N + c];
                const float2 r1v = *(const float2*)&res[(size_t)r1*N + c];
                v00 += r0v.x; v01 += r0v.y; v10 += r1v.x; v11 += r1v.y;
            }
            float2 o0; o0.x = v00; o0.y = v01;
            float2 o1; o1.x = v10; o1.y = v11;
            *(float2*)&C[(size_t)r0*N + c] = o0;
            *(float2*)&C[(size_t)r1*N + c] = o1;
        }
    }
}

// ---------------- Flash attention, TF32 mma + fp32 online softmax (unchanged) --
template<bool CAUSAL>
__global__ __launch_bounds__(256)
void attn_tf32(const float* __restrict__ Qg, const float* __restrict__ Kg,
               const float* __restrict__ Vg, float* __restrict__ Og)
{
    const int AP = 76;
    extern __shared__ float sm[];
    float* Qs   = sm;
    float* Ks   = Qs + 64*AP;
    float* Vs   = Ks + 64*AP;
    float* Ss   = Vs + 64*AP;
    float* mrow = Ss + 64*AP;
    float* lrow = mrow + 64;
    float* arow = lrow + 64;

    const int tid  = threadIdx.x;
    const int lane = tid & 31;
    const int wid  = tid >> 5;
    const int gid  = lane >> 2;
    const int tig  = lane & 3;
    const int wm   = (wid & 3) * 16;
    const int wn   = (wid >> 2) * 32;
    const int qt = blockIdx.x, h = blockIdx.y, b = blockIdx.z;
    const size_t base = (size_t)b*TSEQ*EDIM + (size_t)h*HDIM;

#pragma unroll
    for (int i = 0; i < 4; i++){
        const int t4 = tid + i*256;
        const int r = t4 >> 4;
        const int c = (t4 & 15) << 2;
        const float4 v = *(const float4*)&Qg[base + (size_t)(qt*64 + r)*EDIM + c];
        Qs[r*AP + c + 0] = tf32r(v.x);
        Qs[r*AP + c + 1] = tf32r(v.y);
        Qs[r*AP + c + 2] = tf32r(v.z);
        Qs[r*AP + c + 3] = tf32r(v.w);
    }
    if (tid < 64){ mrow[tid] = -1e30f; lrow[tid] = 0.f; }

    float oacc[4][4];
#pragma unroll
    for (int i = 0; i < 4; i++)
#pragma unroll
        for (int j = 0; j < 4; j++) oacc[i][j] = 0.f;

    const int nkt = CAUSAL ? (qt + 1) : (TSEQ/64);

    for (int kt = 0; kt < nkt; ++kt){
        __syncthreads();
#pragma unroll
        for (int i = 0; i < 4; i++){
            const int t4 = tid + i*256;
            const int r = t4 >> 4;
            const int c = (t4 & 15) << 2;
            const size_t go = base + (size_t)(kt*64 + r)*EDIM + c;
            const float4 kv = *(const float4*)&Kg[go];
            const float4 vv = *(const float4*)&Vg[go];
            Ks[r*AP + c + 0] = tf32r(kv.x);
            Ks[r*AP + c + 1] = tf32r(kv.y);
            Ks[r*AP + c + 2] = tf32r(kv.z);
            Ks[r*AP + c + 3] = tf32r(kv.w);
            Vs[r*AP + c + 0] = tf32r(vv.x);
            Vs[r*AP + c + 1] = tf32r(vv.y);
            Vs[r*AP + c + 2] = tf32r(vv.z);
            Vs[r*AP + c + 3] = tf32r(vv.w);
        }
        __syncthreads();

        float sa[4][4];
#pragma unroll
        for (int na = 0; na < 4; na++)
#pragma unroll
            for (int k = 0; k < 4; k++) sa[na][k] = 0.f;
#pragma unroll
        for (int d8 = 0; d8 < 8; d8++){
            const int d = d8 * 8;
            uint32_t afr[4];
            afr[0] = __float_as_uint(Qs[(wm + gid    )*AP + d + tig]);
            afr[1] = __float_as_uint(Qs[(wm + gid + 8)*AP + d + tig]);
            afr[2] = __float_as_uint(Qs[(wm + gid    )*AP + d + tig + 4]);
            afr[3] = __float_as_uint(Qs[(wm + gid + 8)*AP + d + tig + 4]);
#pragma unroll
            for (int na = 0; na < 4; na++){
                const int kr = wn + na*8 + gid;
                const uint32_t b0 = __float_as_uint(Ks[kr*AP + d + tig]);
                const uint32_t b1 = __float_as_uint(Ks[kr*AP + d + tig + 4]);
                mma_tf32(sa[na], afr, b0, b1);
            }
        }
        {
            const int r0 = wm + gid;
            const int r1 = r0 + 8;
            const int gr0 = qt*64 + r0;
            const int gr1 = qt*64 + r1;
#pragma unroll
            for (int na = 0; na < 4; na++){
                const int col = wn + na*8 + 2*tig;
                const int gc  = kt*64 + col;
                float v00 = sa[na][0] * 0.125f;
                float v01 = sa[na][1] * 0.125f;
                float v10 = sa[na][2] * 0.125f;
                float v11 = sa[na][3] * 0.125f;
                if (CAUSAL){
                    if (gc     > gr0) v00 = -1e30f;
                    if (gc + 1 > gr0) v01 = -1e30f;
                    if (gc     > gr1) v10 = -1e30f;
                    if (gc + 1 > gr1) v11 = -1e30f;
                }
                float2 s0; s0.x = v00; s0.y = v01;
                float2 s1; s1.x = v10; s1.y = v11;
                *(float2*)&Ss[r0*AP + col] = s0;
                *(float2*)&Ss[r1*AP + col] = s1;
            }
        }
        __syncthreads();

        {
            const int r = tid >> 2;
            const int g = tid & 3;
            float* srow = &Ss[r*AP + g*16];
            const float mold = mrow[r];
            float mx = -1e30f;
#pragma unroll
            for (int c = 0; c < 16; c++) mx = fmaxf(mx, srow[c]);
            mx = fmaxf(mx, __shfl_xor_sync(0xffffffffu, mx, 1));
            mx = fmaxf(mx, __shfl_xor_sync(0xffffffffu, mx, 2));
            const float mnew = fmaxf(mold, mx);
            float sum = 0.f;
#pragma unroll
            for (int c = 0; c < 16; c++){
                const float p = __expf(srow[c] - mnew);
                srow[c] = p;
                sum += p;
            }
            sum += __shfl_xor_sync(0xffffffffu, sum, 1);
            sum += __shfl_xor_sync(0xffffffffu, sum, 2);
            if (g == 0){
                const float al = __expf(mold - mnew);
                mrow[r] = mnew;
                lrow[r] = lrow[r]*al + sum;
                arow[r] = al;
            }
        }
        __syncthreads();

        const float al0 = arow[wm + gid];
        const float al1 = arow[wm + gid + 8];
#pragma unroll
        for (int na = 0; na < 4; na++){
            oacc[na][0] *= al0; oacc[na][1] *= al0;
            oacc[na][2] *= al1; oacc[na][3] *= al1;
        }
#pragma unroll
        for (int k8 = 0; k8 < 8; k8++){
            const int kk = k8 * 8;
            uint32_t afr[4];
            afr[0] = tf32u(Ss[(wm + gid    )*AP + kk + tig]);
            afr[1] = tf32u(Ss[(wm + gid + 8)*AP + kk + tig]);
            afr[2] = tf32u(Ss[(wm + gid    )*AP + kk + tig + 4]);
            afr[3] = tf32u(Ss[(wm + gid + 8)*AP + kk + tig + 4]);
#pragma unroll
            for (int na = 0; na < 4; na++){
                const int dc = wn + na*8 + gid;
                const uint32_t b0 = __float_as_uint(Vs[(kk + tig    )*AP + dc]);
                const uint32_t b1 = __float_as_uint(Vs[(kk + tig + 4)*AP + dc]);
                mma_tf32(oacc[na], afr, b0, b1);
            }
        }
    }

    const float li0 = 1.f / lrow[wm + gid];
    const float li1 = 1.f / lrow[wm + gid + 8];
    const int row0 = qt*64 + wm + gid;
    const int row1 = row0 + 8;
#pragma unroll
    for (int na = 0; na < 4; na++){
        const int col = wn + na*8 + 2*tig;
        float2 o0; o0.x = oacc[na][0]*li0; o0.y = oacc[na][1]*li0;
        float2 o1; o1.x = oacc[na][2]*li1; o1.y = oacc[na][3]*li1;
        *(float2*)&Og[base + (size_t)row0*EDIM + col] = o0;
        *(float2*)&Og[base + (size_t)row1*EDIM + col] = o1;
    }
}

// ---------------- launch ----------------
extern "C" void kernel_launch(void* const* d_in, const int* in_sizes, int n_in,
                              void* d_out, int out_size)
{
    const float* x     = (const float*)d_in[0];
    const float* enc   = (const float*)d_in[1];
    const float* sa_wq = (const float*)d_in[3];  const float* sa_bq = (const float*)d_in[4];
    const float* sa_wk = (const float*)d_in[5];  const float* sa_bk = (const float*)d_in[6];
    const float* sa_wv = (const float*)d_in[7];  const float* sa_bv = (const float*)d_in[8];
    const float* sa_wo = (const float*)d_in[9];  const float* sa_bo = (const float*)d_in[10];
    const float* ca_wq = (const float*)d_in[11]; const float* ca_bq = (const float*)d_in[12];
    const float* ca_wk = (const float*)d_in[13]; const float* ca_bk = (const float*)d_in[14];
    const float* ca_wv = (const float*)d_in[15]; const float* ca_bv = (const float*)d_in[16];
    const float* ca_wo = (const float*)d_in[17]; const float* ca_bo = (const float*)d_in[18];
    const float* ff_w1 = (const float*)d_in[19]; const float* ff_b1 = (const float*)d_in[20];
    const float* ff_w2 = (const float*)d_in[21]; const float* ff_b2 = (const float*)d_in[22];
    const float* ln1g  = (const float*)d_in[23]; const float* ln1b  = (const float*)d_in[24];
    const float* ln2g  = (const float*)d_in[25]; const float* ln2b  = (const float*)d_in[26];
    const float* ln3g  = (const float*)d_in[27]; const float* ln3b  = (const float*)d_in[28];
    float* out = (float*)d_out;

    float *h, *q, *k, *v, *ao, *x1, *x2, *ff;
    cudaGetSymbolAddress((void**)&h,  g_h);
    cudaGetSymbolAddress((void**)&q,  g_q);
    cudaGetSymbolAddress((void**)&k,  g_kb);
    cudaGetSymbolAddress((void**)&v,  g_vb);
    cudaGetSymbolAddress((void**)&ao, g_ao);
    cudaGetSymbolAddress((void**)&x1, g_x1);
    cudaGetSymbolAddress((void**)&x2, g_x2);
    cudaGetSymbolAddress((void**)&ff, g_ff);

    const int ATTN_SMEM = (4*64*76 + 3*64) * (int)sizeof(float);
    cudaFuncSetAttribute(attn_tf32<true>,  cudaFuncAttributeMaxDynamicSharedMemorySize, ATTN_SMEM);
    cudaFuncSetAttribute(attn_tf32<false>, cudaFuncAttributeMaxDynamicSharedMemorySize, ATTN_SMEM);

    const dim3 thr(256);
    const dim3 gP (EDIM/128, NTOK/128);
    const dim3 gF1(FFD/128,  NTOK/128);
    const dim3 gA (TSEQ/64, 16, 2);

    ln_kernel<<<NTOK, 256>>>(x, ln1g, ln1b, h);
    gemm_f16<false,false><<<gP, thr>>>(h, sa_wq, sa_bq, nullptr, q, EDIM, EDIM);
    gemm_f16<false,false><<<gP, thr>>>(h, sa_wk, sa_bk, nullptr, k, EDIM, EDIM);
    gemm_f16<false,false><<<gP, thr>>>(h, sa_wv, sa_bv, nullptr, v, EDIM, EDIM);
    attn_tf32<true><<<gA, thr, ATTN_SMEM>>>(q, k, v, ao);
    gemm_f16<false,true ><<<gP, thr>>>(ao, sa_wo, sa_bo, x, x1, EDIM, EDIM);

    ln_kernel<<<NTOK, 256>>>(x1, ln2g, ln2b, h);
    gemm_f16<false,false><<<gP, thr>>>(h,   ca_wq, ca_bq, nullptr, q, EDIM, EDIM);
    gemm_f16<false,false><<<gP, thr>>>(enc, ca_wk, ca_bk, nullptr, k, EDIM, EDIM);
    gemm_f16<false,false><<<gP, thr>>>(enc, ca_wv, ca_bv, nullptr, v, EDIM, EDIM);
    attn_tf32<false><<<gA, thr, ATTN_SMEM>>>(q, k, v, ao);
    gemm_f16<false,true ><<<gP, thr>>>(ao, ca_wo, ca_bo, x1, x2, EDIM, EDIM);

    ln_kernel<<<NTOK, 256>>>(x2, ln3g, ln3b, h);
    gemm_f16<true ,false><<<gF1, thr>>>(h,  ff_w1, ff_b1, nullptr, ff, FFD, EDIM);
    gemm_f16<false,true ><<<gP, thr>>>(ff, ff_w2, ff_b2, x2, out, EDIM, FFD);
}

// round 7
// speedup vs baseline: 3.6568x; 2.0428x over previous
#include <cuda_runtime.h>
#include <cuda_fp16.h>
#include <math.h>
#include <stdint.h>

#define EDIM 1024
#define TSEQ 2048
#define NTOK 4096
#define FFD  4096
#define LN_EPS 1e-5f
#define MEGA 1048576

// half scratch
__device__ __half g_wh [(size_t)16*MEGA];   // 8 proj @1M, ff1 @8M(4M), ff2 @12M(4M)
__device__ __half g_ench[(size_t)NTOK*EDIM];
__device__ __half g_hh [(size_t)NTOK*EDIM];
__device__ __half g_qh [(size_t)NTOK*EDIM];
__device__ __half g_kh [(size_t)NTOK*EDIM];
__device__ __half g_vh [(size_t)NTOK*EDIM];
__device__ __half g_aoh[(size_t)NTOK*EDIM];
__device__ __half g_ffh[(size_t)NTOK*FFD];
// fp32 residual streams
__device__ float  g_x1 [(size_t)NTOK*EDIM];
__device__ float  g_x2 [(size_t)NTOK*EDIM];

// ---------------- primitives ----------------
__device__ __forceinline__ void mma_f16(float* c, const uint32_t* a, uint32_t b0, uint32_t b1){
    asm volatile("mma.sync.aligned.m16n8k16.row.col.f32.f16.f16.f32 "
        "{%0,%1,%2,%3}, {%4,%5,%6,%7}, {%8,%9}, {%0,%1,%2,%3};"
        : "+f"(c[0]), "+f"(c[1]), "+f"(c[2]), "+f"(c[3])
        : "r"(a[0]), "r"(a[1]), "r"(a[2]), "r"(a[3]), "r"(b0), "r"(b1));
}
__device__ __forceinline__ void ldsm4(uint32_t* r, uint32_t a){
    asm volatile("ldmatrix.sync.aligned.m8n8.x4.shared.b16 {%0,%1,%2,%3}, [%4];"
        : "=r"(r[0]), "=r"(r[1]), "=r"(r[2]), "=r"(r[3]) : "r"(a));
}
__device__ __forceinline__ void ldsm4t(uint32_t* r, uint32_t a){
    asm volatile("ldmatrix.sync.aligned.m8n8.x4.trans.shared.b16 {%0,%1,%2,%3}, [%4];"
        : "=r"(r[0]), "=r"(r[1]), "=r"(r[2]), "=r"(r[3]) : "r"(a));
}
__device__ __forceinline__ void cpa16(uint32_t dst, const void* src){
    asm volatile("cp.async.cg.shared.global [%0], [%1], 16;" :: "r"(dst), "l"(src));
}
#define CP_COMMIT() asm volatile("cp.async.commit_group;")
#define CP_WAIT(n)  asm volatile("cp.async.wait_group %0;" :: "n"(n))
__device__ __forceinline__ uint32_t pack2(float lo, float hi){
    __half2 h = __floats2half2_rn(lo, hi);
    return *(uint32_t*)&h;
}

// ---------------- f32 -> f16 convert ----------------
__global__ __launch_bounds__(256)
void f2h(const float* __restrict__ in, __half* __restrict__ out, int n4){
    int i = blockIdx.x*256 + threadIdx.x;
    if (i < n4){
        float4 v = ((const float4*)in)[i];
        ((__half2*)out)[2*i]   = __floats2half2_rn(v.x, v.y);
        ((__half2*)out)[2*i+1] = __floats2half2_rn(v.z, v.w);
    }
}

// ---------------- LayerNorm (fp32 in, half out) ----------------
__global__ __launch_bounds__(256)
void ln_kernel(const float* __restrict__ x, const float* __restrict__ gamma,
               const float* __restrict__ beta, __half* __restrict__ out)
{
    const int row = blockIdx.x;
    const int t = threadIdx.x;
    const float4 v = ((const float4*)(x + (size_t)row*EDIM))[t];
    float s  = v.x + v.y + v.z + v.w;
    float ss = v.x*v.x + v.y*v.y + v.z*v.z + v.w*v.w;
#pragma unroll
    for (int o = 16; o; o >>= 1){
        s  += __shfl_xor_sync(0xffffffffu, s,  o);
        ss += __shfl_xor_sync(0xffffffffu, ss, o);
    }
    __shared__ float sh_s[8], sh_ss[8];
    const int w = t >> 5, l = t & 31;
    if (l == 0){ sh_s[w] = s; sh_ss[w] = ss; }
    __syncthreads();
    if (w == 0){
        s  = (l < 8) ? sh_s[l]  : 0.f;
        ss = (l < 8) ? sh_ss[l] : 0.f;
#pragma unroll
        for (int o = 4; o; o >>= 1){
            s  += __shfl_xor_sync(0xffffffffu, s,  o);
            ss += __shfl_xor_sync(0xffffffffu, ss, o);
        }
        if (l == 0){ sh_s[0] = s; sh_ss[0] = ss; }
    }
    __syncthreads();
    const float mu   = sh_s[0] * (1.f/EDIM);
    const float var  = sh_ss[0] * (1.f/EDIM) - mu*mu;
    const float rstd = rsqrtf(var + LN_EPS);
    const float4 g4 = ((const float4*)gamma)[t];
    const float4 b4 = ((const float4*)beta)[t];
    __half2* orow = (__half2*)(out + (size_t)row*EDIM);
    orow[2*t]   = __floats2half2_rn((v.x-mu)*rstd*g4.x + b4.x, (v.y-mu)*rstd*g4.y + b4.y);
    orow[2*t+1] = __floats2half2_rn((v.z-mu)*rstd*g4.z + b4.z, (v.w-mu)*rstd*g4.w + b4.w);
}

// ---------------- FP16 GEMM (half A, half W), cp.async + ldmatrix ----------
// 128x128 tile, BK=32 double-buffered, 8 warps (4m x 2n), warp 32x64.
template<bool RELU, bool RES, bool OUTH>
__global__ __launch_bounds__(256)
void gemm_h(const __half* __restrict__ A, const __half* __restrict__ W,
            const float* __restrict__ bias, const float* __restrict__ res,
            void* __restrict__ Cv, int N, int K)
{
    __shared__ __half As[2][128*40];   // [m][k] stride 40 halves (32 data + 8 pad)
    __shared__ __half Bs[2][32*136];   // [k][n] stride 136 halves (128 data + 8 pad)

    const int tid  = threadIdx.x;
    const int lane = tid & 31;
    const int wid  = tid >> 5;
    const int gid  = lane >> 2;
    const int tig  = lane & 3;
    const int wm   = (wid & 3) * 32;
    const int wn   = (wid >> 2) * 64;
    const int m0 = blockIdx.y * 128;
    const int n0 = blockIdx.x * 128;

    const uint32_t asb = (uint32_t)__cvta_generic_to_shared(&As[0][0]);
    const uint32_t bsb = (uint32_t)__cvta_generic_to_shared(&Bs[0][0]);

    const int a_r = wm + (lane&7) + ((lane>>3)&1)*8;  // +ma*16
    const int a_k = ((lane>>4)&1)*8;                  // +kc*16
    const int b_k = (lane&7) + ((lane>>3)&1)*8;       // +kc*16
    const int b_n = wn + ((lane>>4)&1)*8;             // +np*16

    float acc[2][8][4];
#pragma unroll
    for (int i=0;i<2;i++)
#pragma unroll
        for (int j=0;j<8;j++)
#pragma unroll
            for (int k=0;k<4;k++) acc[i][j][k]=0.f;

#define LOADSTAGE(b_, kt_) do{                                               \
        _Pragma("unroll")                                                    \
        for (int i=0;i<2;i++){                                               \
            int idx = tid + 256*i;                                           \
            int ar = idx>>2, ac = (idx&3)*8;                                 \
            cpa16(asb + (uint32_t)(((b_)*5120 + ar*40 + ac)*2),              \
                  A + (size_t)(m0+ar)*K + (kt_)*32 + ac);                    \
            int kr = idx>>4, nc = (idx&15)*8;                                \
            cpa16(bsb + (uint32_t)(((b_)*4352 + kr*136 + nc)*2),             \
                  W + (size_t)((kt_)*32+kr)*N + n0 + nc);                    \
        }                                                                    \
        CP_COMMIT();                                                         \
    }while(0)

    LOADSTAGE(0, 0);
    const int KT = K >> 5;
    for (int kt = 0; kt < KT; ++kt){
        CP_WAIT(0);
        __syncthreads();
        const int buf = kt & 1;
        if (kt + 1 < KT) LOADSTAGE(buf^1, kt+1);
        const uint32_t asb_b = asb + (uint32_t)(buf*5120*2);
        const uint32_t bsb_b = bsb + (uint32_t)(buf*4352*2);
#pragma unroll
        for (int kc = 0; kc < 2; kc++){
            uint32_t af[2][4];
#pragma unroll
            for (int ma = 0; ma < 2; ma++)
                ldsm4(af[ma], asb_b + (uint32_t)(((a_r + ma*16)*40 + a_k + kc*16)*2));
#pragma unroll
            for (int np = 0; np < 4; np++){
                uint32_t bf[4];
                ldsm4t(bf, bsb_b + (uint32_t)(((b_k + kc*16)*136 + b_n + np*16)*2));
                mma_f16(acc[0][2*np  ], af[0], bf[0], bf[1]);
                mma_f16(acc[0][2*np+1], af[0], bf[2], bf[3]);
                mma_f16(acc[1][2*np  ], af[1], bf[0], bf[1]);
                mma_f16(acc[1][2*np+1], af[1], bf[2], bf[3]);
            }
        }
    }
#undef LOADSTAGE

#pragma unroll
    for (int ma = 0; ma < 2; ma++){
        const int r0 = m0 + wm + ma*16 + gid;
        const int r1 = r0 + 8;
#pragma unroll
        for (int na = 0; na < 8; na++){
            const int c = n0 + wn + na*8 + 2*tig;
            const float2 bb = *(const float2*)&bias[c];
            float v00 = acc[ma][na][0] + bb.x;
            float v01 = acc[ma][na][1] + bb.y;
            float v10 = acc[ma][na][2] + bb.x;
            float v11 = acc[ma][na][3] + bb.y;
            if (RELU){
                v00 = fmaxf(v00,0.f); v01 = fmaxf(v01,0.f);
                v10 = fmaxf(v10,0.f); v11 = fmaxf(v11,0.f);
            }
            if (RES){
                const float2 q0 = *(const float2*)&res[(size_t)r0*N + c];
                const float2 q1 = *(const float2*)&res[(size_t)r1*N + c];
                v00 += q0.x; v01 += q0.y; v10 += q1.x; v11 += q1.y;
            }
            if (OUTH){
                __half* Ch = (__half*)Cv;
                *(__half2*)&Ch[(size_t)r0*N + c] = __floats2half2_rn(v00, v01);
                *(__half2*)&Ch[(size_t)r1*N + c] = __floats2half2_rn(v10, v11);
            } else {
                float* Cf = (float*)Cv;
                float2 o0; o0.x=v00; o0.y=v01;
                float2 o1; o1.x=v10; o1.y=v11;
                *(float2*)&Cf[(size_t)r0*N + c] = o0;
                *(float2*)&Cf[(size_t)r1*N + c] = o1;
            }
        }
    }
}

// ---------------- Flash attention fp16, P-in-registers ----------------
// Block = 128 q rows for one (b,h); 8 warps, each warp 16 rows x full 64 keys/dims.
// Row stride 72 halves (64 data + 8 pad). Dynamic smem (55296 B).
#define ATP 72
#define KVB (64*ATP)      // 4608 halves per K/V buffer
template<bool CAUSAL>
__global__ __launch_bounds__(256)
void attn_h(const __half* __restrict__ Qg, const __half* __restrict__ Kg,
            const __half* __restrict__ Vg, __half* __restrict__ Og)
{
    extern __shared__ __half smh[];
    __half* Qs = smh;                  // [128][ATP]
    __half* Ks = Qs + 128*ATP;         // [2][64][ATP]
    __half* Vs = Ks + 2*KVB;           // [2][64][ATP]

    const int tid  = threadIdx.x;
    const int lane = tid & 31;
    const int wid  = tid >> 5;
    const int gid  = lane >> 2;
    const int tig  = lane & 3;
    const int wm   = wid * 16;
    const int qb = blockIdx.x, h = blockIdx.y, b = blockIdx.z;
    const size_t base = (size_t)b*TSEQ*EDIM + (size_t)h*64;

    const uint32_t qsb = (uint32_t)__cvta_generic_to_shared(Qs);
    const uint32_t ksb = (uint32_t)__cvta_generic_to_shared(Ks);
    const uint32_t vsb = (uint32_t)__cvta_generic_to_shared(Vs);

    // Q tile: 128 rows x 64 halves
#pragma unroll
    for (int i = 0; i < 4; i++){
        int idx = tid + 256*i;
        int r = idx>>3, c = (idx&7)*8;
        cpa16(qsb + (uint32_t)((r*ATP + c)*2), Qg + base + (size_t)(qb*128 + r)*EDIM + c);
    }
    CP_COMMIT();
#define LOADKV(b_, kt_) do{                                                   \
        _Pragma("unroll")                                                     \
        for (int i = 0; i < 2; i++){                                          \
            int idx = tid + 256*i;                                            \
            int r = idx>>3, c = (idx&7)*8;                                    \
            size_t go = base + (size_t)((kt_)*64 + r)*EDIM + c;               \
            uint32_t so = (uint32_t)(((b_)*KVB + r*ATP + c)*2);               \
            cpa16(ksb + so, Kg + go);                                         \
            cpa16(vsb + so, Vg + go);                                         \
        }                                                                     \
        CP_COMMIT();                                                          \
    }while(0)
    LOADKV(0, 0);
    CP_WAIT(1);
    __syncthreads();

    const int q_r = wm + (lane&7) + ((lane>>3)&1)*8;
    const int q_k = ((lane>>4)&1)*8;
    uint32_t qf[4][4];
#pragma unroll
    for (int kc = 0; kc < 4; kc++)
        ldsm4(qf[kc], qsb + (uint32_t)((q_r*ATP + q_k + kc*16)*2));

    const int k_r = (lane&7);                     // + na*8 key rows
    const int k_c = (lane>>3)*8;                  // + kq*32 dims
    const int v_r = (lane&7) + ((lane>>3)&1)*8;   // + kc*16 key rows
    const int v_n = ((lane>>4)&1)*8;              // + np*16 dims

    float oacc[8][4];
#pragma unroll
    for (int i=0;i<8;i++)
#pragma unroll
        for (int j=0;j<4;j++) oacc[i][j]=0.f;
    float m0=-1e30f, m1=-1e30f, l0=0.f, l1=0.f;

    const int nkt = CAUSAL ? (2*qb + 2) : (TSEQ/64);
    const int gr0 = qb*128 + wm + gid;
    const int gr1 = gr0 + 8;

    for (int kt = 0; kt < nkt; ++kt){
        CP_WAIT(0);
        __syncthreads();
        const int buf = kt & 1;
        if (kt + 1 < nkt) LOADKV(buf^1, kt+1);
        const uint32_t ksb_b = ksb + (uint32_t)(buf*KVB*2);
        const uint32_t vsb_b = vsb + (uint32_t)(buf*KVB*2);

        // S = Q K^T
        float sa[8][4];
#pragma unroll
        for (int na=0;na<8;na++)
#pragma unroll
            for (int e=0;e<4;e++) sa[na][e]=0.f;
#pragma unroll
        for (int na = 0; na < 8; na++){
#pragma unroll
            for (int kq = 0; kq < 2; kq++){
                uint32_t kf[4];
                ldsm4(kf, ksb_b + (uint32_t)(((na*8 + k_r)*ATP + kq*32 + k_c)*2));
                mma_f16(sa[na], qf[2*kq  ], kf[0], kf[1]);
                mma_f16(sa[na], qf[2*kq+1], kf[2], kf[3]);
            }
        }
        // scale + causal mask
#pragma unroll
        for (int na = 0; na < 8; na++){
            const int c0 = kt*64 + na*8 + 2*tig;
#pragma unroll
            for (int e = 0; e < 4; e++){
                float v = sa[na][e] * 0.125f;
                if (CAUSAL){
                    const int col = c0 + (e&1);
                    const int row = (e<2) ? gr0 : gr1;
                    if (col > row) v = -1e30f;
                }
                sa[na][e] = v;
            }
        }
        // online softmax over register rows
        float mx0=-1e30f, mx1=-1e30f;
#pragma unroll
        for (int na=0;na<8;na++){
            mx0 = fmaxf(mx0, fmaxf(sa[na][0], sa[na][1]));
            mx1 = fmaxf(mx1, fmaxf(sa[na][2], sa[na][3]));
        }
        mx0 = fmaxf(mx0, __shfl_xor_sync(0xffffffffu, mx0, 1));
        mx0 = fmaxf(mx0, __shfl_xor_sync(0xffffffffu, mx0, 2));
        mx1 = fmaxf(mx1, __shfl_xor_sync(0xffffffffu, mx1, 1));
        mx1 = fmaxf(mx1, __shfl_xor_sync(0xffffffffu, mx1, 2));
        const float mn0 = fmaxf(m0, mx0);
        const float mn1 = fmaxf(m1, mx1);
        const float al0 = __expf(m0 - mn0);
        const float al1 = __expf(m1 - mn1);
        float s0 = 0.f, s1 = 0.f;
#pragma unroll
        for (int na=0;na<8;na++){
            sa[na][0] = __expf(sa[na][0] - mn0);
            sa[na][1] = __expf(sa[na][1] - mn0);
            sa[na][2] = __expf(sa[na][2] - mn1);
            sa[na][3] = __expf(sa[na][3] - mn1);
            s0 += sa[na][0] + sa[na][1];
            s1 += sa[na][2] + sa[na][3];
        }
        s0 += __shfl_xor_sync(0xffffffffu, s0, 1);
        s0 += __shfl_xor_sync(0xffffffffu, s0, 2);
        s1 += __shfl_xor_sync(0xffffffffu, s1, 1);
        s1 += __shfl_xor_sync(0xffffffffu, s1, 2);
        m0 = mn0; m1 = mn1;
        l0 = l0*al0 + s0;
        l1 = l1*al1 + s1;
        // P fragments straight from accumulators (A-fragment layout)
        uint32_t pf[4][4];
#pragma unroll
        for (int kc = 0; kc < 4; kc++){
            pf[kc][0] = pack2(sa[2*kc  ][0], sa[2*kc  ][1]);
            pf[kc][1] = pack2(sa[2*kc  ][2], sa[2*kc  ][3]);
            pf[kc][2] = pack2(sa[2*kc+1][0], sa[2*kc+1][1]);
            pf[kc][3] = pack2(sa[2*kc+1][2], sa[2*kc+1][3]);
        }
#pragma unroll
        for (int na=0;na<8;na++){
            oacc[na][0]*=al0; oacc[na][1]*=al0;
            oacc[na][2]*=al1; oacc[na][3]*=al1;
        }
        // O += P V
#pragma unroll
        for (int kc = 0; kc < 4; kc++){
#pragma unroll
            for (int np = 0; np < 4; np++){
                uint32_t vf[4];
                ldsm4t(vf, vsb_b + (uint32_t)(((kc*16 + v_r)*ATP + v_n + np*16)*2));
                mma_f16(oacc[2*np  ], pf[kc], vf[0], vf[1]);
                mma_f16(oacc[2*np+1], pf[kc], vf[2], vf[3]);
            }
        }
    }
#undef LOADKV

    const float li0 = 1.f / l0;
    const float li1 = 1.f / l1;
#pragma unroll
    for (int na = 0; na < 8; na++){
        const int c = na*8 + 2*tig;
        *(__half2*)&Og[base + (size_t)gr0*EDIM + c] =
            __floats2half2_rn(oacc[na][0]*li0, oacc[na][1]*li0);
        *(__half2*)&Og[base + (size_t)gr1*EDIM + c] =
            __floats2half2_rn(oacc[na][2]*li1, oacc[na][3]*li1);
    }
}

// ---------------- launch ----------------
extern "C" void kernel_launch(void* const* d_in, const int* in_sizes, int n_in,
                              void* d_out, int out_size)
{
    const float* x     = (const float*)d_in[0];
    const float* enc   = (const float*)d_in[1];
    const float* sa_wq = (const float*)d_in[3];  const float* sa_bq = (const float*)d_in[4];
    const float* sa_wk = (const float*)d_in[5];  const float* sa_bk = (const float*)d_in[6];
    const float* sa_wv = (const float*)d_in[7];  const float* sa_bv = (const float*)d_in[8];
    const float* sa_wo = (const float*)d_in[9];  const float* sa_bo = (const float*)d_in[10];
    const float* ca_wq = (const float*)d_in[11]; const float* ca_bq = (const float*)d_in[12];
    const float* ca_wk = (const float*)d_in[13]; const float* ca_bk = (const float*)d_in[14];
    const float* ca_wv = (const float*)d_in[15]; const float* ca_bv = (const float*)d_in[16];
    const float* ca_wo = (const float*)d_in[17]; const float* ca_bo = (const float*)d_in[18];
    const float* ff_w1 = (const float*)d_in[19]; const float* ff_b1 = (const float*)d_in[20];
    const float* ff_w2 = (const float*)d_in[21]; const float* ff_b2 = (const float*)d_in[22];
    const float* ln1g  = (const float*)d_in[23]; const float* ln1b  = (const float*)d_in[24];
    const float* ln2g  = (const float*)d_in[25]; const float* ln2b  = (const float*)d_in[26];
    const float* ln3g  = (const float*)d_in[27]; const float* ln3b  = (const float*)d_in[28];
    float* out = (float*)d_out;

    __half *wh, *ench, *hh, *qh, *kh, *vh, *aoh, *ffh;
    float *x1, *x2;
    cudaGetSymbolAddress((void**)&wh,   g_wh);
    cudaGetSymbolAddress((void**)&ench, g_ench);
    cudaGetSymbolAddress((void**)&hh,   g_hh);
    cudaGetSymbolAddress((void**)&qh,   g_qh);
    cudaGetSymbolAddress((void**)&kh,   g_kh);
    cudaGetSymbolAddress((void**)&vh,   g_vh);
    cudaGetSymbolAddress((void**)&aoh,  g_aoh);
    cudaGetSymbolAddress((void**)&ffh,  g_ffh);
    cudaGetSymbolAddress((void**)&x1,   g_x1);
    cudaGetSymbolAddress((void**)&x2,   g_x2);

    const int ATTN_SMEM = (128*ATP + 4*KVB) * 2;   // 55296 B
    cudaFuncSetAttribute(attn_h<true>,  cudaFuncAttributeMaxDynamicSharedMemorySize, ATTN_SMEM);
    cudaFuncSetAttribute(attn_h<false>, cudaFuncAttributeMaxDynamicSharedMemorySize, ATTN_SMEM);

    const int CB = 256;
    const int n4p = MEGA/4, n4f = MEGA;
    f2h<<<(n4p+CB-1)/CB, CB>>>(sa_wq, wh + 0*(size_t)MEGA, n4p);
    f2h<<<(n4p+CB-1)/CB, CB>>>(sa_wk, wh + 1*(size_t)MEGA, n4p);
    f2h<<<(n4p+CB-1)/CB, CB>>>(sa_wv, wh + 2*(size_t)MEGA, n4p);
    f2h<<<(n4p+CB-1)/CB, CB>>>(sa_wo, wh + 3*(size_t)MEGA, n4p);
    f2h<<<(n4p+CB-1)/CB, CB>>>(ca_wq, wh + 4*(size_t)MEGA, n4p);
    f2h<<<(n4p+CB-1)/CB, CB>>>(ca_wk, wh + 5*(size_t)MEGA, n4p);
    f2h<<<(n4p+CB-1)/CB, CB>>>(ca_wv, wh + 6*(size_t)MEGA, n4p);
    f2h<<<(n4p+CB-1)/CB, CB>>>(ca_wo, wh + 7*(size_t)MEGA, n4p);
    f2h<<<(n4f+CB-1)/CB, CB>>>(ff_w1, wh + 8*(size_t)MEGA, n4f);
    f2h<<<(n4f+CB-1)/CB, CB>>>(ff_w2, wh + 12*(size_t)MEGA, n4f);
    f2h<<<(n4f+CB-1)/CB, CB>>>(enc,   ench, n4f);

    const dim3 thr(256);
    const dim3 gP (EDIM/128, NTOK/128);    // 8 x 32
    const dim3 gF1(FFD/128,  NTOK/128);    // 32 x 32
    const dim3 gA (TSEQ/128, 16, 2);       // 16 x 16 x 2

    // ---- self attention ----
    ln_kernel<<<NTOK, 256>>>(x, ln1g, ln1b, hh);
    gemm_h<false,false,true ><<<gP, thr>>>(hh, wh+0*(size_t)MEGA, sa_bq, nullptr, qh, EDIM, EDIM);
    gemm_h<false,false,true ><<<gP, thr>>>(hh, wh+1*(size_t)MEGA, sa_bk, nullptr, kh, EDIM, EDIM);
    gemm_h<false,false,true ><<<gP, thr>>>(hh, wh+2*(size_t)MEGA, sa_bv, nullptr, vh, EDIM, EDIM);
    attn_h<true><<<gA, thr, ATTN_SMEM>>>(qh, kh, vh, aoh);
    gemm_h<false,true ,false><<<gP, thr>>>(aoh, wh+3*(size_t)MEGA, sa_bo, x, x1, EDIM, EDIM);

    // ---- cross attention ----
    ln_kernel<<<NTOK, 256>>>(x1, ln2g, ln2b, hh);
    gemm_h<false,false,true ><<<gP, thr>>>(hh,   wh+4*(size_t)MEGA, ca_bq, nullptr, qh, EDIM, EDIM);
    gemm_h<false,false,true ><<<gP, thr>>>(ench, wh+5*(size_t)MEGA, ca_bk, nullptr, kh, EDIM, EDIM);
    gemm_h<false,false,true ><<<gP, thr>>>(ench, wh+6*(size_t)MEGA, ca_bv, nullptr, vh, EDIM, EDIM);
    attn_h<false><<<gA, thr, ATTN_SMEM>>>(qh, kh, vh, aoh);
    gemm_h<false,true ,false><<<gP, thr>>>(aoh, wh+7*(size_t)MEGA, ca_bo, x1, x2, EDIM, EDIM);

    // ---- feed-forward ----
    ln_kernel<<<NTOK, 256>>>(x2, ln3g, ln3b, hh);
    gemm_h<true ,false,true ><<<gF1, thr>>>(hh,  wh+8*(size_t)MEGA,  ff_b1, nullptr, ffh, FFD, EDIM);
    gemm_h<false,true ,false><<<gP, thr>>>(ffh, wh+12*(size_t)MEGA, ff_b2, x2, out, EDIM, FFD);
}

// round 8
// speedup vs baseline: 3.7393x; 1.0226x over previous
#include <cuda_runtime.h>
#include <cuda_fp16.h>
#include <math.h>
#include <stdint.h>

#define EDIM 1024
#define TSEQ 2048
#define NTOK 4096
#define FFD  4096
#define LN_EPS 1e-5f
#define MEGA 1048576

// half scratch
__device__ __half g_wh  [(size_t)16*MEGA]; // sa_qkv@0(3M) sa_wo@3M ca_wq@4M ca_kv@5M(2M) ca_wo@7M ff1@8M(4M) ff2@12M(4M)
__device__ __half g_ench[(size_t)NTOK*EDIM];
__device__ __half g_hh  [(size_t)NTOK*EDIM];
__device__ __half g_qkvh[(size_t)12*MEGA];  // self: [4096][3072]; reused cross: [4096][2048]
__device__ __half g_qh  [(size_t)NTOK*EDIM];
__device__ __half g_aoh [(size_t)NTOK*EDIM];
__device__ __half g_ffh [(size_t)NTOK*FFD];
__device__ float  g_x1  [(size_t)NTOK*EDIM];
__device__ float  g_x2  [(size_t)NTOK*EDIM];
__device__ float  g_bqkv[3072];
__device__ float  g_bkv [2048];

// ---------------- primitives ----------------
__device__ __forceinline__ void mma_f16(float* c, const uint32_t* a, uint32_t b0, uint32_t b1){
    asm volatile("mma.sync.aligned.m16n8k16.row.col.f32.f16.f16.f32 "
        "{%0,%1,%2,%3}, {%4,%5,%6,%7}, {%8,%9}, {%0,%1,%2,%3};"
        : "+f"(c[0]), "+f"(c[1]), "+f"(c[2]), "+f"(c[3])
        : "r"(a[0]), "r"(a[1]), "r"(a[2]), "r"(a[3]), "r"(b0), "r"(b1));
}
__device__ __forceinline__ void ldsm4(uint32_t* r, uint32_t a){
    asm volatile("ldmatrix.sync.aligned.m8n8.x4.shared.b16 {%0,%1,%2,%3}, [%4];"
        : "=r"(r[0]), "=r"(r[1]), "=r"(r[2]), "=r"(r[3]) : "r"(a));
}
__device__ __forceinline__ void ldsm4t(uint32_t* r, uint32_t a){
    asm volatile("ldmatrix.sync.aligned.m8n8.x4.trans.shared.b16 {%0,%1,%2,%3}, [%4];"
        : "=r"(r[0]), "=r"(r[1]), "=r"(r[2]), "=r"(r[3]) : "r"(a));
}
__device__ __forceinline__ void cpa16(uint32_t dst, const void* src){
    asm volatile("cp.async.cg.shared.global [%0], [%1], 16;" :: "r"(dst), "l"(src));
}
#define CP_COMMIT() asm volatile("cp.async.commit_group;")
#define CP_WAIT(n)  asm volatile("cp.async.wait_group %0;" :: "n"(n))
__device__ __forceinline__ uint32_t pack2(float lo, float hi){
    __half2 h = __floats2half2_rn(lo, hi);
    return *(uint32_t*)&h;
}

// ---------------- mega convert: all f32->f16 weights + enc + bias concat ------
// float4-granular segments; remapped writes build fused QKV / KV weight layouts.
#define SEGP 262144            // 1M floats / 4
__global__ __launch_bounds__(256)
void cvt_all(const float* __restrict__ sa_wq, const float* __restrict__ sa_wk,
             const float* __restrict__ sa_wv, const float* __restrict__ sa_wo,
             const float* __restrict__ ca_wq, const float* __restrict__ ca_wk,
             const float* __restrict__ ca_wv, const float* __restrict__ ca_wo,
             const float* __restrict__ ff_w1, const float* __restrict__ ff_w2,
             const float* __restrict__ enc,
             const float* __restrict__ sa_bq, const float* __restrict__ sa_bk,
             const float* __restrict__ sa_bv,
             const float* __restrict__ ca_bk, const float* __restrict__ ca_bv,
             __half* __restrict__ wh, __half* __restrict__ ench,
             float* __restrict__ bqkv, float* __restrict__ bkv)
{
    const long i = (long)blockIdx.x*256 + threadIdx.x;
    // [0, 8*SEGP): eight 1024x1024 weights
    if (i < 8L*SEGP){
        const int seg = (int)(i / SEGP);
        const int li  = (int)(i % SEGP);
        const float4 v = ((const float4*)(seg==0?sa_wq: seg==1?sa_wk: seg==2?sa_wv:
                          seg==3?sa_wo: seg==4?ca_wq: seg==5?ca_wk: seg==6?ca_wv:ca_wo))[li];
        uint2 o; o.x = pack2(v.x, v.y); o.y = pack2(v.z, v.w);
        size_t d;
        const int row = li >> 8, n = (li & 255) * 4;
        if (seg <= 2)       d = (size_t)row*3072 + seg*1024 + n;             // sa qkv fused
        else if (seg == 3)  d = (size_t)3*MEGA + (size_t)li*4;
        else if (seg == 4)  d = (size_t)4*MEGA + (size_t)li*4;
        else if (seg <= 6)  d = (size_t)5*MEGA + (size_t)row*2048 + (seg-5)*1024 + n; // ca kv fused
        else                d = (size_t)7*MEGA + (size_t)li*4;
        *(uint2*)&wh[d] = o;
        return;
    }
    // ff1 / ff2 / enc: 1M float4 each
    if (i < 11L*SEGP*1 + 0L){ /* fallthrough structured below */ }
    long j = i - 8L*SEGP;
    if (j < (long)MEGA){            // ff1 (4M floats)
        const float4 v = ((const float4*)ff_w1)[j];
        uint2 o; o.x = pack2(v.x,v.y); o.y = pack2(v.z,v.w);
        *(uint2*)&wh[(size_t)8*MEGA + (size_t)j*4] = o;
        return;
    }
    j -= MEGA;
    if (j < (long)MEGA){            // ff2
        const float4 v = ((const float4*)ff_w2)[j];
        uint2 o; o.x = pack2(v.x,v.y); o.y = pack2(v.z,v.w);
        *(uint2*)&wh[(size_t)12*MEGA + (size_t)j*4] = o;
        return;
    }
    j -= MEGA;
    if (j < (long)MEGA){            // enc
        const float4 v = ((const float4*)enc)[j];
        uint2 o; o.x = pack2(v.x,v.y); o.y = pack2(v.z,v.w);
        *(uint2*)&ench[(size_t)j*4] = o;
        return;
    }
    j -= MEGA;
    if (j < 768){                   // sa bias concat (3*1024 floats)
        const int e = (int)j * 4;
        const int sub = e >> 10, idx = e & 1023;
        const float4 v = *(const float4*)&((sub==0?sa_bq: sub==1?sa_bk:sa_bv)[idx]);
        *(float4*)&bqkv[e] = v;
        return;
    }
    j -= 768;
    if (j < 512){                   // ca kv bias concat
        const int e = (int)j * 4;
        const int sub = e >> 10, idx = e & 1023;
        const float4 v = *(const float4*)&((sub==0?ca_bk:ca_bv)[idx]);
        *(float4*)&bkv[e] = v;
    }
}

// ---------------- LayerNorm (fp32 in, half out) ----------------
__global__ __launch_bounds__(256)
void ln_kernel(const float* __restrict__ x, const float* __restrict__ gamma,
               const float* __restrict__ beta, __half* __restrict__ out)
{
    const int row = blockIdx.x;
    const int t = threadIdx.x;
    const float4 v = ((const float4*)(x + (size_t)row*EDIM))[t];
    float s  = v.x + v.y + v.z + v.w;
    float ss = v.x*v.x + v.y*v.y + v.z*v.z + v.w*v.w;
#pragma unroll
    for (int o = 16; o; o >>= 1){
        s  += __shfl_xor_sync(0xffffffffu, s,  o);
        ss += __shfl_xor_sync(0xffffffffu, ss, o);
    }
    __shared__ float sh_s[8], sh_ss[8];
    const int w = t >> 5, l = t & 31;
    if (l == 0){ sh_s[w] = s; sh_ss[w] = ss; }
    __syncthreads();
    if (w == 0){
        s  = (l < 8) ? sh_s[l]  : 0.f;
        ss = (l < 8) ? sh_ss[l] : 0.f;
#pragma unroll
        for (int o = 4; o; o >>= 1){
            s  += __shfl_xor_sync(0xffffffffu, s,  o);
            ss += __shfl_xor_sync(0xffffffffu, ss, o);
        }
        if (l == 0){ sh_s[0] = s; sh_ss[0] = ss; }
    }
    __syncthreads();
    const float mu   = sh_s[0] * (1.f/EDIM);
    const float var  = sh_ss[0] * (1.f/EDIM) - mu*mu;
    const float rstd = rsqrtf(var + LN_EPS);
    const float4 g4 = ((const float4*)gamma)[t];
    const float4 b4 = ((const float4*)beta)[t];
    __half2* orow = (__half2*)(out + (size_t)row*EDIM);
    orow[2*t]   = __floats2half2_rn((v.x-mu)*rstd*g4.x + b4.x, (v.y-mu)*rstd*g4.y + b4.y);
    orow[2*t+1] = __floats2half2_rn((v.z-mu)*rstd*g4.z + b4.z, (v.w-mu)*rstd*g4.w + b4.w);
}

// ---------------- FP16 GEMM (half A, half W), cp.async + ldmatrix ----------
template<bool RELU, bool RES, bool OUTH>
__global__ __launch_bounds__(256)
void gemm_h(const __half* __restrict__ A, const __half* __restrict__ W,
            const float* __restrict__ bias, const float* __restrict__ res,
            void* __restrict__ Cv, int N, int K)
{
    __shared__ __half As[2][128*40];
    __shared__ __half Bs[2][32*136];

    const int tid  = threadIdx.x;
    const int lane = tid & 31;
    const int wid  = tid >> 5;
    const int gid  = lane >> 2;
    const int tig  = lane & 3;
    const int wm   = (wid & 3) * 32;
    const int wn   = (wid >> 2) * 64;
    const int m0 = blockIdx.y * 128;
    const int n0 = blockIdx.x * 128;

    const uint32_t asb = (uint32_t)__cvta_generic_to_shared(&As[0][0]);
    const uint32_t bsb = (uint32_t)__cvta_generic_to_shared(&Bs[0][0]);

    const int a_r = wm + (lane&7) + ((lane>>3)&1)*8;
    const int a_k = ((lane>>4)&1)*8;
    const int b_k = (lane&7) + ((lane>>3)&1)*8;
    const int b_n = wn + ((lane>>4)&1)*8;

    float acc[2][8][4];
#pragma unroll
    for (int i=0;i<2;i++)
#pragma unroll
        for (int j=0;j<8;j++)
#pragma unroll
            for (int k=0;k<4;k++) acc[i][j][k]=0.f;

#define LOADSTAGE(b_, kt_) do{                                               \
        _Pragma("unroll")                                                    \
        for (int i=0;i<2;i++){                                               \
            int idx = tid + 256*i;                                           \
            int ar = idx>>2, ac = (idx&3)*8;                                 \
            cpa16(asb + (uint32_t)(((b_)*5120 + ar*40 + ac)*2),              \
                  A + (size_t)(m0+ar)*K + (kt_)*32 + ac);                    \
            int kr = idx>>4, nc = (idx&15)*8;                                \
            cpa16(bsb + (uint32_t)(((b_)*4352 + kr*136 + nc)*2),             \
                  W + (size_t)((kt_)*32+kr)*N + n0 + nc);                    \
        }                                                                    \
        CP_COMMIT();                                                         \
    }while(0)

    LOADSTAGE(0, 0);
    const int KT = K >> 5;
    for (int kt = 0; kt < KT; ++kt){
        CP_WAIT(0);
        __syncthreads();
        const int buf = kt & 1;
        if (kt + 1 < KT) LOADSTAGE(buf^1, kt+1);
        const uint32_t asb_b = asb + (uint32_t)(buf*5120*2);
        const uint32_t bsb_b = bsb + (uint32_t)(buf*4352*2);
#pragma unroll
        for (int kc = 0; kc < 2; kc++){
            uint32_t af[2][4];
#pragma unroll
            for (int ma = 0; ma < 2; ma++)
                ldsm4(af[ma], asb_b + (uint32_t)(((a_r + ma*16)*40 + a_k + kc*16)*2));
#pragma unroll
            for (int np = 0; np < 4; np++){
                uint32_t bf[4];
                ldsm4t(bf, bsb_b + (uint32_t)(((b_k + kc*16)*136 + b_n + np*16)*2));
                mma_f16(acc[0][2*np  ], af[0], bf[0], bf[1]);
                mma_f16(acc[0][2*np+1], af[0], bf[2], bf[3]);
                mma_f16(acc[1][2*np  ], af[1], bf[0], bf[1]);
                mma_f16(acc[1][2*np+1], af[1], bf[2], bf[3]);
            }
        }
    }
#undef LOADSTAGE

#pragma unroll
    for (int ma = 0; ma < 2; ma++){
        const int r0 = m0 + wm + ma*16 + gid;
        const int r1 = r0 + 8;
#pragma unroll
        for (int na = 0; na < 8; na++){
            const int c = n0 + wn + na*8 + 2*tig;
            const float2 bb = *(const float2*)&bias[c];
            float v00 = acc[ma][na][0] + bb.x;
            float v01 = acc[ma][na][1] + bb.y;
            float v10 = acc[ma][na][2] + bb.x;
            float v11 = acc[ma][na][3] + bb.y;
            if (RELU){
                v00 = fmaxf(v00,0.f); v01 = fmaxf(v01,0.f);
                v10 = fmaxf(v10,0.f); v11 = fmaxf(v11,0.f);
            }
            if (RES){
                const float2 q0 = *(const float2*)&res[(size_t)r0*N + c];
                const float2 q1 = *(const float2*)&res[(size_t)r1*N + c];
                v00 += q0.x; v01 += q0.y; v10 += q1.x; v11 += q1.y;
            }
            if (OUTH){
                __half* Ch = (__half*)Cv;
                *(__half2*)&Ch[(size_t)r0*N + c] = __floats2half2_rn(v00, v01);
                *(__half2*)&Ch[(size_t)r1*N + c] = __floats2half2_rn(v10, v11);
            } else {
                float* Cf = (float*)Cv;
                float2 o0; o0.x=v00; o0.y=v01;
                float2 o1; o1.x=v10; o1.y=v11;
                *(float2*)&Cf[(size_t)r0*N + c] = o0;
                *(float2*)&Cf[(size_t)r1*N + c] = o1;
            }
        }
    }
}

// ---------------- Flash attention fp16, P-in-registers, runtime strides ------
#define ATP 72
#define KVB (64*ATP)
template<bool CAUSAL>
__global__ __launch_bounds__(256)
void attn_h(const __half* __restrict__ Qg, const __half* __restrict__ Kg,
            const __half* __restrict__ Vg, __half* __restrict__ Og,
            int ldq, int ldkv)
{
    extern __shared__ __half smh[];
    __half* Qs = smh;
    __half* Ks = Qs + 128*ATP;
    __half* Vs = Ks + 2*KVB;

    const int tid  = threadIdx.x;
    const int lane = tid & 31;
    const int wid  = tid >> 5;
    const int gid  = lane >> 2;
    const int tig  = lane & 3;
    const int wm   = wid * 16;
    const int qb = blockIdx.x, h = blockIdx.y, b = blockIdx.z;
    const size_t baseq = (size_t)b*TSEQ*ldq  + (size_t)h*64;
    const size_t basek = (size_t)b*TSEQ*ldkv + (size_t)h*64;
    const size_t baseo = (size_t)b*TSEQ*EDIM + (size_t)h*64;

    const uint32_t qsb = (uint32_t)__cvta_generic_to_shared(Qs);
    const uint32_t ksb = (uint32_t)__cvta_generic_to_shared(Ks);
    const uint32_t vsb = (uint32_t)__cvta_generic_to_shared(Vs);

#pragma unroll
    for (int i = 0; i < 4; i++){
        int idx = tid + 256*i;
        int r = idx>>3, c = (idx&7)*8;
        cpa16(qsb + (uint32_t)((r*ATP + c)*2), Qg + baseq + (size_t)(qb*128 + r)*ldq + c);
    }
    CP_COMMIT();
#define LOADKV(b_, kt_) do{                                                   \
        _Pragma("unroll")                                                     \
        for (int i = 0; i < 2; i++){                                          \
            int idx = tid + 256*i;                                            \
            int r = idx>>3, c = (idx&7)*8;                                    \
            size_t go = basek + (size_t)((kt_)*64 + r)*ldkv + c;              \
            uint32_t so = (uint32_t)(((b_)*KVB + r*ATP + c)*2);               \
            cpa16(ksb + so, Kg + go);                                         \
            cpa16(vsb + so, Vg + go);                                         \
        }                                                                     \
        CP_COMMIT();                                                          \
    }while(0)
    LOADKV(0, 0);
    CP_WAIT(1);
    __syncthreads();

    const int q_r = wm + (lane&7) + ((lane>>3)&1)*8;
    const int q_k = ((lane>>4)&1)*8;
    uint32_t qf[4][4];
#pragma unroll
    for (int kc = 0; kc < 4; kc++)
        ldsm4(qf[kc], qsb + (uint32_t)((q_r*ATP + q_k + kc*16)*2));

    const int k_r = (lane&7);
    const int k_c = (lane>>3)*8;
    const int v_r = (lane&7) + ((lane>>3)&1)*8;
    const int v_n = ((lane>>4)&1)*8;

    float oacc[8][4];
#pragma unroll
    for (int i=0;i<8;i++)
#pragma unroll
        for (int j=0;j<4;j++) oacc[i][j]=0.f;
    float m0=-1e30f, m1=-1e30f, l0=0.f, l1=0.f;

    const int nkt = CAUSAL ? (2*qb + 2) : (TSEQ/64);
    const int gr0 = qb*128 + wm + gid;
    const int gr1 = gr0 + 8;

    for (int kt = 0; kt < nkt; ++kt){
        CP_WAIT(0);
        __syncthreads();
        const int buf = kt & 1;
        if (kt + 1 < nkt) LOADKV(buf^1, kt+1);
        const uint32_t ksb_b = ksb + (uint32_t)(buf*KVB*2);
        const uint32_t vsb_b = vsb + (uint32_t)(buf*KVB*2);

        float sa[8][4];
#pragma unroll
        for (int na=0;na<8;na++)
#pragma unroll
            for (int e=0;e<4;e++) sa[na][e]=0.f;
#pragma unroll
        for (int na = 0; na < 8; na++){
#pragma unroll
            for (int kq = 0; kq < 2; kq++){
                uint32_t kf[4];
                ldsm4(kf, ksb_b + (uint32_t)(((na*8 + k_r)*ATP + kq*32 + k_c)*2));
                mma_f16(sa[na], qf[2*kq  ], kf[0], kf[1]);
                mma_f16(sa[na], qf[2*kq+1], kf[2], kf[3]);
            }
        }
#pragma unroll
        for (int na = 0; na < 8; na++){
            const int c0 = kt*64 + na*8 + 2*tig;
#pragma unroll
            for (int e = 0; e < 4; e++){
                float v = sa[na][e] * 0.125f;
                if (CAUSAL){
                    const int col = c0 + (e&1);
                    const int row = (e<2) ? gr0 : gr1;
                    if (col > row) v = -1e30f;
                }
                sa[na][e] = v;
            }
        }
        float mx0=-1e30f, mx1=-1e30f;
#pragma unroll
        for (int na=0;na<8;na++){
            mx0 = fmaxf(mx0, fmaxf(sa[na][0], sa[na][1]));
            mx1 = fmaxf(mx1, fmaxf(sa[na][2], sa[na][3]));
        }
        mx0 = fmaxf(mx0, __shfl_xor_sync(0xffffffffu, mx0, 1));
        mx0 = fmaxf(mx0, __shfl_xor_sync(0xffffffffu, mx0, 2));
        mx1 = fmaxf(mx1, __shfl_xor_sync(0xffffffffu, mx1, 1));
        mx1 = fmaxf(mx1, __shfl_xor_sync(0xffffffffu, mx1, 2));
        const float mn0 = fmaxf(m0, mx0);
        const float mn1 = fmaxf(m1, mx1);
        const float al0 = __expf(m0 - mn0);
        const float al1 = __expf(m1 - mn1);
        float s0 = 0.f, s1 = 0.f;
#pragma unroll
        for (int na=0;na<8;na++){
            sa[na][0] = __expf(sa[na][0] - mn0);
            sa[na][1] = __expf(sa[na][1] - mn0);
            sa[na][2] = __expf(sa[na][2] - mn1);
            sa[na][3] = __expf(sa[na][3] - mn1);
            s0 += sa[na][0] + sa[na][1];
            s1 += sa[na][2] + sa[na][3];
        }
        s0 += __shfl_xor_sync(0xffffffffu, s0, 1);
        s0 += __shfl_xor_sync(0xffffffffu, s0, 2);
        s1 += __shfl_xor_sync(0xffffffffu, s1, 1);
        s1 += __shfl_xor_sync(0xffffffffu, s1, 2);
        m0 = mn0; m1 = mn1;
        l0 = l0*al0 + s0;
        l1 = l1*al1 + s1;
        uint32_t pf[4][4];
#pragma unroll
        for (int kc = 0; kc < 4; kc++){
            pf[kc][0] = pack2(sa[2*kc  ][0], sa[2*kc  ][1]);
            pf[kc][1] = pack2(sa[2*kc  ][2], sa[2*kc  ][3]);
            pf[kc][2] = pack2(sa[2*kc+1][0], sa[2*kc+1][1]);
            pf[kc][3] = pack2(sa[2*kc+1][2], sa[2*kc+1][3]);
        }
#pragma unroll
        for (int na=0;na<8;na++){
            oacc[na][0]*=al0; oacc[na][1]*=al0;
            oacc[na][2]*=al1; oacc[na][3]*=al1;
        }
#pragma unroll
        for (int kc = 0; kc < 4; kc++){
#pragma unroll
            for (int np = 0; np < 4; np++){
                uint32_t vf[4];
                ldsm4t(vf, vsb_b + (uint32_t)(((kc*16 + v_r)*ATP + v_n + np*16)*2));
                mma_f16(oacc[2*np  ], pf[kc], vf[0], vf[1]);
                mma_f16(oacc[2*np+1], pf[kc], vf[2], vf[3]);
            }
        }
    }
#undef LOADKV

    const float li0 = 1.f / l0;
    const float li1 = 1.f / l1;
#pragma unroll
    for (int na = 0; na < 8; na++){
        const int c = na*8 + 2*tig;
        *(__half2*)&Og[baseo + (size_t)gr0*EDIM + c] =
            __floats2half2_rn(oacc[na][0]*li0, oacc[na][1]*li0);
        *(__half2*)&Og[baseo + (size_t)gr1*EDIM + c] =
            __floats2half2_rn(oacc[na][2]*li1, oacc[na][3]*li1);
    }
}

// ---------------- launch ----------------
extern "C" void kernel_launch(void* const* d_in, const int* in_sizes, int n_in,
                              void* d_out, int out_size)
{
    const float* x     = (const float*)d_in[0];
    const float* enc   = (const float*)d_in[1];
    const float* sa_wq = (const float*)d_in[3];  const float* sa_bq = (const float*)d_in[4];
    const float* sa_wk = (const float*)d_in[5];  const float* sa_bk = (const float*)d_in[6];
    const float* sa_wv = (const float*)d_in[7];  const float* sa_bv = (const float*)d_in[8];
    const float* sa_wo = (const float*)d_in[9];  const float* sa_bo = (const float*)d_in[10];
    const float* ca_wq = (const float*)d_in[11]; const float* ca_bq = (const float*)d_in[12];
    const float* ca_wk = (const float*)d_in[13]; const float* ca_bk = (const float*)d_in[14];
    const float* ca_wv = (const float*)d_in[15]; const float* ca_bv = (const float*)d_in[16];
    const float* ca_wo = (const float*)d_in[17]; const float* ca_bo = (const float*)d_in[18];
    const float* ff_w1 = (const float*)d_in[19]; const float* ff_b1 = (const float*)d_in[20];
    const float* ff_w2 = (const float*)d_in[21]; const float* ff_b2 = (const float*)d_in[22];
    const float* ln1g  = (const float*)d_in[23]; const float* ln1b  = (const float*)d_in[24];
    const float* ln2g  = (const float*)d_in[25]; const float* ln2b  = (const float*)d_in[26];
    const float* ln3g  = (const float*)d_in[27]; const float* ln3b  = (const float*)d_in[28];
    float* out = (float*)d_out;

    __half *wh, *ench, *hh, *qkvh, *qh, *aoh, *ffh;
    float *x1, *x2, *bqkv, *bkv;
    cudaGetSymbolAddress((void**)&wh,   g_wh);
    cudaGetSymbolAddress((void**)&ench, g_ench);
    cudaGetSymbolAddress((void**)&hh,   g_hh);
    cudaGetSymbolAddress((void**)&qkvh, g_qkvh);
    cudaGetSymbolAddress((void**)&qh,   g_qh);
    cudaGetSymbolAddress((void**)&aoh,  g_aoh);
    cudaGetSymbolAddress((void**)&ffh,  g_ffh);
    cudaGetSymbolAddress((void**)&x1,   g_x1);
    cudaGetSymbolAddress((void**)&x2,   g_x2);
    cudaGetSymbolAddress((void**)&bqkv, g_bqkv);
    cudaGetSymbolAddress((void**)&bkv,  g_bkv);

    const int ATTN_SMEM = (128*ATP + 4*KVB) * 2;   // 55296 B
    cudaFuncSetAttribute(attn_h<true>,  cudaFuncAttributeMaxDynamicSharedMemorySize, ATTN_SMEM);
    cudaFuncSetAttribute(attn_h<false>, cudaFuncAttributeMaxDynamicSharedMemorySize, ATTN_SMEM);

    // one conversion launch: 8*SEGP + 3*MEGA + 1280 float4 items
    const long cvt_total = 8L*SEGP + 3L*MEGA + 1280;
    cvt_all<<<(unsigned)((cvt_total + 255)/256), 256>>>(
        sa_wq, sa_wk, sa_wv, sa_wo, ca_wq, ca_wk, ca_wv, ca_wo,
        ff_w1, ff_w2, enc, sa_bq, sa_bk, sa_bv, ca_bk, ca_bv,
        wh, ench, bqkv, bkv);

    const dim3 thr(256);
    const dim3 gQKV(3072/128, NTOK/128);   // 24 x 32
    const dim3 gKV (2048/128, NTOK/128);   // 16 x 32
    const dim3 gP  (EDIM/128, NTOK/128);   // 8 x 32
    const dim3 gF1 (FFD/128,  NTOK/128);   // 32 x 32
    const dim3 gA  (TSEQ/128, 16, 2);      // 16 x 16 x 2

    // ---- self attention ----
    ln_kernel<<<NTOK, 256>>>(x, ln1g, ln1b, hh);
    gemm_h<false,false,true ><<<gQKV, thr>>>(hh, wh, bqkv, nullptr, qkvh, 3072, 1024);
    attn_h<true><<<gA, thr, ATTN_SMEM>>>(qkvh, qkvh+1024, qkvh+2048, aoh, 3072, 3072);
    gemm_h<false,true ,false><<<gP, thr>>>(aoh, wh+(size_t)3*MEGA, sa_bo, x, x1, EDIM, EDIM);

    // ---- cross attention ----
    ln_kernel<<<NTOK, 256>>>(x1, ln2g, ln2b, hh);
    gemm_h<false,false,true ><<<gP,  thr>>>(hh,   wh+(size_t)4*MEGA, ca_bq, nullptr, qh,   EDIM, 1024);
    gemm_h<false,false,true ><<<gKV, thr>>>(ench, wh+(size_t)5*MEGA, bkv,   nullptr, qkvh, 2048, 1024);
    attn_h<false><<<gA, thr, ATTN_SMEM>>>(qh, qkvh, qkvh+1024, aoh, 1024, 2048);
    gemm_h<false,true ,false><<<gP, thr>>>(aoh, wh+(size_t)7*MEGA, ca_bo, x1, x2, EDIM, EDIM);

    // ---- feed-forward ----
    ln_kernel<<<NTOK, 256>>>(x2, ln3g, ln3b, hh);
    gemm_h<true ,false,true ><<<gF1, thr>>>(hh,  wh+(size_t)8*MEGA,  ff_b1, nullptr, ffh, FFD, 1024);
    gemm_h<false,true ,false><<<gP, thr>>>(ffh, wh+(size_t)12*MEGA, ff_b2, x2, out, EDIM, FFD);
}

// round 9
// speedup vs baseline: 4.0360x; 1.0793x over previous
#include <cuda_runtime.h>
#include <cuda_fp16.h>
#include <math.h>
#include <stdint.h>

#define EDIM 1024
#define TSEQ 2048
#define NTOK 4096
#define FFD  4096
#define LN_EPS 1e-5f
#define MEGA 1048576

__device__ __half g_wh  [(size_t)16*MEGA];
__device__ __half g_ench[(size_t)NTOK*EDIM];
__device__ __half g_hh  [(size_t)NTOK*EDIM];
__device__ __half g_qkvh[(size_t)12*MEGA];
__device__ __half g_qh  [(size_t)NTOK*EDIM];
__device__ __half g_aoh [(size_t)NTOK*EDIM];
__device__ __half g_ffh [(size_t)NTOK*FFD];
__device__ float  g_x1  [(size_t)NTOK*EDIM];
__device__ float  g_x2  [(size_t)NTOK*EDIM];
__device__ float  g_bqkv[3072];
__device__ float  g_bkv [2048];

// ---------------- primitives ----------------
__device__ __forceinline__ void mma_f16(float* c, const uint32_t* a, uint32_t b0, uint32_t b1){
    asm volatile("mma.sync.aligned.m16n8k16.row.col.f32.f16.f16.f32 "
        "{%0,%1,%2,%3}, {%4,%5,%6,%7}, {%8,%9}, {%0,%1,%2,%3};"
        : "+f"(c[0]), "+f"(c[1]), "+f"(c[2]), "+f"(c[3])
        : "r"(a[0]), "r"(a[1]), "r"(a[2]), "r"(a[3]), "r"(b0), "r"(b1));
}
__device__ __forceinline__ void ldsm4(uint32_t* r, uint32_t a){
    asm volatile("ldmatrix.sync.aligned.m8n8.x4.shared.b16 {%0,%1,%2,%3}, [%4];"
        : "=r"(r[0]), "=r"(r[1]), "=r"(r[2]), "=r"(r[3]) : "r"(a));
}
__device__ __forceinline__ void ldsm4t(uint32_t* r, uint32_t a){
    asm volatile("ldmatrix.sync.aligned.m8n8.x4.trans.shared.b16 {%0,%1,%2,%3}, [%4];"
        : "=r"(r[0]), "=r"(r[1]), "=r"(r[2]), "=r"(r[3]) : "r"(a));
}
__device__ __forceinline__ void cpa16(uint32_t dst, const void* src){
    asm volatile("cp.async.cg.shared.global [%0], [%1], 16;" :: "r"(dst), "l"(src));
}
#define CP_COMMIT() asm volatile("cp.async.commit_group;")
#define CP_WAIT(n)  asm volatile("cp.async.wait_group %0;" :: "n"(n))
__device__ __forceinline__ uint32_t pack2(float lo, float hi){
    __half2 h = __floats2half2_rn(lo, hi);
    return *(uint32_t*)&h;
}
__device__ __forceinline__ uint32_t pexp2(float lo, float hi){
    __half2 h = h2exp2(__floats2half2_rn(lo, hi));
    return *(uint32_t*)&h;
}
#define HONES 0x3C003C00u

// ---------------- mega convert ----------------
#define SEGP 262144
__global__ __launch_bounds__(256)
void cvt_all(const float* __restrict__ sa_wq, const float* __restrict__ sa_wk,
             const float* __restrict__ sa_wv, const float* __restrict__ sa_wo,
             const float* __restrict__ ca_wq, const float* __restrict__ ca_wk,
             const float* __restrict__ ca_wv, const float* __restrict__ ca_wo,
             const float* __restrict__ ff_w1, const float* __restrict__ ff_w2,
             const float* __restrict__ enc,
             const float* __restrict__ sa_bq, const float* __restrict__ sa_bk,
             const float* __restrict__ sa_bv,
             const float* __restrict__ ca_bk, const float* __restrict__ ca_bv,
             __half* __restrict__ wh, __half* __restrict__ ench,
             float* __restrict__ bqkv, float* __restrict__ bkv)
{
    const long i = (long)blockIdx.x*256 + threadIdx.x;
    if (i < 8L*SEGP){
        const int seg = (int)(i / SEGP);
        const int li  = (int)(i % SEGP);
        const float4 v = ((const float4*)(seg==0?sa_wq: seg==1?sa_wk: seg==2?sa_wv:
                          seg==3?sa_wo: seg==4?ca_wq: seg==5?ca_wk: seg==6?ca_wv:ca_wo))[li];
        uint2 o; o.x = pack2(v.x, v.y); o.y = pack2(v.z, v.w);
        size_t d;
        const int row = li >> 8, n = (li & 255) * 4;
        if (seg <= 2)       d = (size_t)row*3072 + seg*1024 + n;
        else if (seg == 3)  d = (size_t)3*MEGA + (size_t)li*4;
        else if (seg == 4)  d = (size_t)4*MEGA + (size_t)li*4;
        else if (seg <= 6)  d = (size_t)5*MEGA + (size_t)row*2048 + (seg-5)*1024 + n;
        else                d = (size_t)7*MEGA + (size_t)li*4;
        *(uint2*)&wh[d] = o;
        return;
    }
    long j = i - 8L*SEGP;
    if (j < (long)MEGA){
        const float4 v = ((const float4*)ff_w1)[j];
        uint2 o; o.x = pack2(v.x,v.y); o.y = pack2(v.z,v.w);
        *(uint2*)&wh[(size_t)8*MEGA + (size_t)j*4] = o;
        return;
    }
    j -= MEGA;
    if (j < (long)MEGA){
        const float4 v = ((const float4*)ff_w2)[j];
        uint2 o; o.x = pack2(v.x,v.y); o.y = pack2(v.z,v.w);
        *(uint2*)&wh[(size_t)12*MEGA + (size_t)j*4] = o;
        return;
    }
    j -= MEGA;
    if (j < (long)MEGA){
        const float4 v = ((const float4*)enc)[j];
        uint2 o; o.x = pack2(v.x,v.y); o.y = pack2(v.z,v.w);
        *(uint2*)&ench[(size_t)j*4] = o;
        return;
    }
    j -= MEGA;
    if (j < 768){
        const int e = (int)j * 4;
        const int sub = e >> 10, idx = e & 1023;
        const float4 v = *(const float4*)&((sub==0?sa_bq: sub==1?sa_bk:sa_bv)[idx]);
        *(float4*)&bqkv[e] = v;
        return;
    }
    j -= 768;
    if (j < 512){
        const int e = (int)j * 4;
        const int sub = e >> 10, idx = e & 1023;
        const float4 v = *(const float4*)&((sub==0?ca_bk:ca_bv)[idx]);
        *(float4*)&bkv[e] = v;
    }
}

// ---------------- LayerNorm (fp32 in, half out) ----------------
__global__ __launch_bounds__(256)
void ln_kernel(const float* __restrict__ x, const float* __restrict__ gamma,
               const float* __restrict__ beta, __half* __restrict__ out)
{
    const int row = blockIdx.x;
    const int t = threadIdx.x;
    const float4 v = ((const float4*)(x + (size_t)row*EDIM))[t];
    float s  = v.x + v.y + v.z + v.w;
    float ss = v.x*v.x + v.y*v.y + v.z*v.z + v.w*v.w;
#pragma unroll
    for (int o = 16; o; o >>= 1){
        s  += __shfl_xor_sync(0xffffffffu, s,  o);
        ss += __shfl_xor_sync(0xffffffffu, ss, o);
    }
    __shared__ float sh_s[8], sh_ss[8];
    const int w = t >> 5, l = t & 31;
    if (l == 0){ sh_s[w] = s; sh_ss[w] = ss; }
    __syncthreads();
    if (w == 0){
        s  = (l < 8) ? sh_s[l]  : 0.f;
        ss = (l < 8) ? sh_ss[l] : 0.f;
#pragma unroll
        for (int o = 4; o; o >>= 1){
            s  += __shfl_xor_sync(0xffffffffu, s,  o);
            ss += __shfl_xor_sync(0xffffffffu, ss, o);
        }
        if (l == 0){ sh_s[0] = s; sh_ss[0] = ss; }
    }
    __syncthreads();
    const float mu   = sh_s[0] * (1.f/EDIM);
    const float var  = sh_ss[0] * (1.f/EDIM) - mu*mu;
    const float rstd = rsqrtf(var + LN_EPS);
    const float4 g4 = ((const float4*)gamma)[t];
    const float4 b4 = ((const float4*)beta)[t];
    __half2* orow = (__half2*)(out + (size_t)row*EDIM);
    orow[2*t]   = __floats2half2_rn((v.x-mu)*rstd*g4.x + b4.x, (v.y-mu)*rstd*g4.y + b4.y);
    orow[2*t+1] = __floats2half2_rn((v.z-mu)*rstd*g4.z + b4.z, (v.w-mu)*rstd*g4.w + b4.w);
}

// ---------------- FP16 GEMM, 3-stage cp.async + ldmatrix ----------
#define ASTG 5120
#define BSTG 4352
#define GEMM_SMEM ((3*ASTG + 3*BSTG)*2)
template<bool RELU, bool RES, bool OUTH>
__global__ __launch_bounds__(256,2)
void gemm_h(const __half* __restrict__ A, const __half* __restrict__ W,
            const float* __restrict__ bias, const float* __restrict__ res,
            void* __restrict__ Cv, int N, int K)
{
    extern __shared__ __half gsm[];
    __half* As = gsm;             // 3 x ASTG
    __half* Bs = gsm + 3*ASTG;    // 3 x BSTG

    const int tid  = threadIdx.x;
    const int lane = tid & 31;
    const int wid  = tid >> 5;
    const int gid  = lane >> 2;
    const int tig  = lane & 3;
    const int wm   = (wid & 3) * 32;
    const int wn   = (wid >> 2) * 64;
    const int m0 = blockIdx.y * 128;
    const int n0 = blockIdx.x * 128;

    const uint32_t asb = (uint32_t)__cvta_generic_to_shared(As);
    const uint32_t bsb = (uint32_t)__cvta_generic_to_shared(Bs);

    const int a_r = wm + (lane&7) + ((lane>>3)&1)*8;
    const int a_k = ((lane>>4)&1)*8;
    const int b_k = (lane&7) + ((lane>>3)&1)*8;
    const int b_n = wn + ((lane>>4)&1)*8;

    float acc[2][8][4];
#pragma unroll
    for (int i=0;i<2;i++)
#pragma unroll
        for (int j=0;j<8;j++)
#pragma unroll
            for (int k=0;k<4;k++) acc[i][j][k]=0.f;

#define LOADSTAGE(b_, kt_) do{                                               \
        _Pragma("unroll")                                                    \
        for (int i=0;i<2;i++){                                               \
            int idx = tid + 256*i;                                           \
            int ar = idx>>2, ac = (idx&3)*8;                                 \
            cpa16(asb + (uint32_t)(((b_)*ASTG + ar*40 + ac)*2),              \
                  A + (size_t)(m0+ar)*K + (kt_)*32 + ac);                    \
            int kr = idx>>4, nc = (idx&15)*8;                                \
            cpa16(bsb + (uint32_t)(((b_)*BSTG + kr*136 + nc)*2),             \
                  W + (size_t)((kt_)*32+kr)*N + n0 + nc);                    \
        }                                                                    \
        CP_COMMIT();                                                         \
    }while(0)

    LOADSTAGE(0, 0);
    LOADSTAGE(1, 1);
    const int KT = K >> 5;
    for (int kt = 0; kt < KT; ++kt){
        CP_WAIT(1);
        __syncthreads();
        if (kt + 2 < KT) LOADSTAGE((kt+2)%3, kt+2);
        else CP_COMMIT();
        const int buf = kt % 3;
        const uint32_t asb_b = asb + (uint32_t)(buf*ASTG*2);
        const uint32_t bsb_b = bsb + (uint32_t)(buf*BSTG*2);
#pragma unroll
        for (int kc = 0; kc < 2; kc++){
            uint32_t af[2][4];
#pragma unroll
            for (int ma = 0; ma < 2; ma++)
                ldsm4(af[ma], asb_b + (uint32_t)(((a_r + ma*16)*40 + a_k + kc*16)*2));
#pragma unroll
            for (int np = 0; np < 4; np++){
                uint32_t bf[4];
                ldsm4t(bf, bsb_b + (uint32_t)(((b_k + kc*16)*136 + b_n + np*16)*2));
                mma_f16(acc[0][2*np  ], af[0], bf[0], bf[1]);
                mma_f16(acc[0][2*np+1], af[0], bf[2], bf[3]);
                mma_f16(acc[1][2*np  ], af[1], bf[0], bf[1]);
                mma_f16(acc[1][2*np+1], af[1], bf[2], bf[3]);
            }
        }
    }
#undef LOADSTAGE

#pragma unroll
    for (int ma = 0; ma < 2; ma++){
        const int r0 = m0 + wm + ma*16 + gid;
        const int r1 = r0 + 8;
#pragma unroll
        for (int na = 0; na < 8; na++){
            const int c = n0 + wn + na*8 + 2*tig;
            const float2 bb = *(const float2*)&bias[c];
            float v00 = acc[ma][na][0] + bb.x;
            float v01 = acc[ma][na][1] + bb.y;
            float v10 = acc[ma][na][2] + bb.x;
            float v11 = acc[ma][na][3] + bb.y;
            if (RELU){
                v00 = fmaxf(v00,0.f); v01 = fmaxf(v01,0.f);
                v10 = fmaxf(v10,0.f); v11 = fmaxf(v11,0.f);
            }
            if (RES){
                const float2 q0 = *(const float2*)&res[(size_t)r0*N + c];
                const float2 q1 = *(const float2*)&res[(size_t)r1*N + c];
                v00 += q0.x; v01 += q0.y; v10 += q1.x; v11 += q1.y;
            }
            if (OUTH){
                __half* Ch = (__half*)Cv;
                *(__half2*)&Ch[(size_t)r0*N + c] = __floats2half2_rn(v00, v01);
                *(__half2*)&Ch[(size_t)r1*N + c] = __floats2half2_rn(v10, v11);
            } else {
                float* Cf = (float*)Cv;
                float2 o0; o0.x=v00; o0.y=v01;
                float2 o1; o1.x=v10; o1.y=v11;
                *(float2*)&Cf[(size_t)r0*N + c] = o0;
                *(float2*)&Cf[(size_t)r1*N + c] = o1;
            }
        }
    }
}

// ---------------- Flash attention fp16, log2-domain softmax ----------------
#define ATP 72
#define KVB (64*ATP)
#define ATTN_SMEM ((128*ATP + 4*KVB)*2)
template<bool CAUSAL>
__global__ __launch_bounds__(256,2)
void attn_h(const __half* __restrict__ Qg, const __half* __restrict__ Kg,
            const __half* __restrict__ Vg, __half* __restrict__ Og,
            int ldq, int ldkv)
{
    extern __shared__ __half smh[];
    __half* Qs = smh;
    __half* Ks = Qs + 128*ATP;
    __half* Vs = Ks + 2*KVB;

    const int tid  = threadIdx.x;
    const int lane = tid & 31;
    const int wid  = tid >> 5;
    const int gid  = lane >> 2;
    const int tig  = lane & 3;
    const int wm   = wid * 16;
    // heavy causal blocks first for better tail packing
    const int qb = CAUSAL ? ((int)gridDim.x - 1 - (int)blockIdx.x) : (int)blockIdx.x;
    const int h = blockIdx.y, b = blockIdx.z;
    const size_t baseq = (size_t)b*TSEQ*ldq  + (size_t)h*64;
    const size_t basek = (size_t)b*TSEQ*ldkv + (size_t)h*64;
    const size_t baseo = (size_t)b*TSEQ*EDIM + (size_t)h*64;

    const uint32_t qsb = (uint32_t)__cvta_generic_to_shared(Qs);
    const uint32_t ksb = (uint32_t)__cvta_generic_to_shared(Ks);
    const uint32_t vsb = (uint32_t)__cvta_generic_to_shared(Vs);

#pragma unroll
    for (int i = 0; i < 4; i++){
        int idx = tid + 256*i;
        int r = idx>>3, c = (idx&7)*8;
        cpa16(qsb + (uint32_t)((r*ATP + c)*2), Qg + baseq + (size_t)(qb*128 + r)*ldq + c);
    }
    CP_COMMIT();
#define LOADKV(b_, kt_) do{                                                   \
        _Pragma("unroll")                                                     \
        for (int i = 0; i < 2; i++){                                          \
            int idx = tid + 256*i;                                            \
            int r = idx>>3, c = (idx&7)*8;                                    \
            size_t go = basek + (size_t)((kt_)*64 + r)*ldkv + c;              \
            uint32_t so = (uint32_t)(((b_)*KVB + r*ATP + c)*2);               \
            cpa16(ksb + so, Kg + go);                                         \
            cpa16(vsb + so, Vg + go);                                         \
        }                                                                     \
        CP_COMMIT();                                                          \
    }while(0)
    LOADKV(0, 0);
    CP_WAIT(1);
    __syncthreads();

    const int q_r = wm + (lane&7) + ((lane>>3)&1)*8;
    const int q_k = ((lane>>4)&1)*8;
    uint32_t qf[4][4];
#pragma unroll
    for (int kc = 0; kc < 4; kc++)
        ldsm4(qf[kc], qsb + (uint32_t)((q_r*ATP + q_k + kc*16)*2));

    const int k_r = (lane&7);
    const int k_c = (lane>>3)*8;
    const int v_r = (lane&7) + ((lane>>3)&1)*8;
    const int v_n = ((lane>>4)&1)*8;

    float oacc[8][4];
#pragma unroll
    for (int i=0;i<8;i++)
#pragma unroll
        for (int j=0;j<4;j++) oacc[i][j]=0.f;
    float m0=-1e30f, m1=-1e30f, l0=0.f, l1=0.f;

    const int nkt = CAUSAL ? (2*qb + 2) : (TSEQ/64);
    const int gr0 = qb*128 + wm + gid;
    const int gr1 = gr0 + 8;
    const float SC = 0.125f * 1.44269504f;   // scale * log2(e)

    for (int kt = 0; kt < nkt; ++kt){
        CP_WAIT(0);
        __syncthreads();
        const int buf = kt & 1;
        if (kt + 1 < nkt) LOADKV(buf^1, kt+1);
        const uint32_t ksb_b = ksb + (uint32_t)(buf*KVB*2);
        const uint32_t vsb_b = vsb + (uint32_t)(buf*KVB*2);

        float sa[8][4];
#pragma unroll
        for (int na=0;na<8;na++)
#pragma unroll
            for (int e=0;e<4;e++) sa[na][e]=0.f;
#pragma unroll
        for (int na = 0; na < 8; na++){
#pragma unroll
            for (int kq = 0; kq < 2; kq++){
                uint32_t kf[4];
                ldsm4(kf, ksb_b + (uint32_t)(((na*8 + k_r)*ATP + kq*32 + k_c)*2));
                mma_f16(sa[na], qf[2*kq  ], kf[0], kf[1]);
                mma_f16(sa[na], qf[2*kq+1], kf[2], kf[3]);
            }
        }
        // scale into log2 domain
#pragma unroll
        for (int na = 0; na < 8; na++)
#pragma unroll
            for (int e = 0; e < 4; e++) sa[na][e] *= SC;
        // causal mask only on diagonal tiles
        if (CAUSAL && kt >= 2*qb){
#pragma unroll
            for (int na = 0; na < 8; na++){
                const int c0 = kt*64 + na*8 + 2*tig;
#pragma unroll
                for (int e = 0; e < 4; e++){
                    const int col = c0 + (e&1);
                    const int row = (e<2) ? gr0 : gr1;
                    if (col > row) sa[na][e] = -1e30f;
                }
            }
        }
        // row max
        float mx0=-1e30f, mx1=-1e30f;
#pragma unroll
        for (int na=0;na<8;na++){
            mx0 = fmaxf(mx0, fmaxf(sa[na][0], sa[na][1]));
            mx1 = fmaxf(mx1, fmaxf(sa[na][2], sa[na][3]));
        }
        mx0 = fmaxf(mx0, __shfl_xor_sync(0xffffffffu, mx0, 1));
        mx0 = fmaxf(mx0, __shfl_xor_sync(0xffffffffu, mx0, 2));
        mx1 = fmaxf(mx1, __shfl_xor_sync(0xffffffffu, mx1, 1));
        mx1 = fmaxf(mx1, __shfl_xor_sync(0xffffffffu, mx1, 2));
        const float mn0 = fmaxf(m0, mx0);
        const float mn1 = fmaxf(m1, mx1);
        const float al0 = exp2f(m0 - mn0);
        const float al1 = exp2f(m1 - mn1);
        m0 = mn0; m1 = mn1;
        // P = 2^(S'-m') directly as fp16 fragments (half2 exp)
        uint32_t pf[4][4];
#pragma unroll
        for (int kc = 0; kc < 4; kc++){
            pf[kc][0] = pexp2(sa[2*kc  ][0]-mn0, sa[2*kc  ][1]-mn0);
            pf[kc][1] = pexp2(sa[2*kc  ][2]-mn1, sa[2*kc  ][3]-mn1);
            pf[kc][2] = pexp2(sa[2*kc+1][0]-mn0, sa[2*kc+1][1]-mn0);
            pf[kc][3] = pexp2(sa[2*kc+1][2]-mn1, sa[2*kc+1][3]-mn1);
        }
        // row sums via ones-mma (consistent with fp16 P used in PV)
        float lacc[4] = {0.f, 0.f, 0.f, 0.f};
#pragma unroll
        for (int kc = 0; kc < 4; kc++)
            mma_f16(lacc, pf[kc], HONES, HONES);
        l0 = l0*al0 + lacc[0];
        l1 = l1*al1 + lacc[2];
        // rescale O, then O += P V
#pragma unroll
        for (int na=0;na<8;na++){
            oacc[na][0]*=al0; oacc[na][1]*=al0;
            oacc[na][2]*=al1; oacc[na][3]*=al1;
        }
#pragma unroll
        for (int kc = 0; kc < 4; kc++){
#pragma unroll
            for (int np = 0; np < 4; np++){
                uint32_t vf[4];
                ldsm4t(vf, vsb_b + (uint32_t)(((kc*16 + v_r)*ATP + v_n + np*16)*2));
                mma_f16(oacc[2*np  ], pf[kc], vf[0], vf[1]);
                mma_f16(oacc[2*np+1], pf[kc], vf[2], vf[3]);
            }
        }
    }
#undef LOADKV

    const float li0 = 1.f / l0;
    const float li1 = 1.f / l1;
#pragma unroll
    for (int na = 0; na < 8; na++){
        const int c = na*8 + 2*tig;
        *(__half2*)&Og[baseo + (size_t)gr0*EDIM + c] =
            __floats2half2_rn(oacc[na][0]*li0, oacc[na][1]*li0);
        *(__half2*)&Og[baseo + (size_t)gr1*EDIM + c] =
            __floats2half2_rn(oacc[na][2]*li1, oacc[na][3]*li1);
    }
}

// ---------------- launch ----------------
extern "C" void kernel_launch(void* const* d_in, const int* in_sizes, int n_in,
                              void* d_out, int out_size)
{
    const float* x     = (const float*)d_in[0];
    const float* enc   = (const float*)d_in[1];
    const float* sa_wq = (const float*)d_in[3];  const float* sa_bq = (const float*)d_in[4];
    const float* sa_wk = (const float*)d_in[5];  const float* sa_bk = (const float*)d_in[6];
    const float* sa_wv = (const float*)d_in[7];  const float* sa_bv = (const float*)d_in[8];
    const float* sa_wo = (const float*)d_in[9];  const float* sa_bo = (const float*)d_in[10];
    const float* ca_wq = (const float*)d_in[11]; const float* ca_bq = (const float*)d_in[12];
    const float* ca_wk = (const float*)d_in[13]; const float* ca_bk = (const float*)d_in[14];
    const float* ca_wv = (const float*)d_in[15]; const float* ca_bv = (const float*)d_in[16];
    const float* ca_wo = (const float*)d_in[17]; const float* ca_bo = (const float*)d_in[18];
    const float* ff_w1 = (const float*)d_in[19]; const float* ff_b1 = (const float*)d_in[20];
    const float* ff_w2 = (const float*)d_in[21]; const float* ff_b2 = (const float*)d_in[22];
    const float* ln1g  = (const float*)d_in[23]; const float* ln1b  = (const float*)d_in[24];
    const float* ln2g  = (const float*)d_in[25]; const float* ln2b  = (const float*)d_in[26];
    const float* ln3g  = (const float*)d_in[27]; const float* ln3b  = (const float*)d_in[28];
    float* out = (float*)d_out;

    __half *wh, *ench, *hh, *qkvh, *qh, *aoh, *ffh;
    float *x1, *x2, *bqkv, *bkv;
    cudaGetSymbolAddress((void**)&wh,   g_wh);
    cudaGetSymbolAddress((void**)&ench, g_ench);
    cudaGetSymbolAddress((void**)&hh,   g_hh);
    cudaGetSymbolAddress((void**)&qkvh, g_qkvh);
    cudaGetSymbolAddress((void**)&qh,   g_qh);
    cudaGetSymbolAddress((void**)&aoh,  g_aoh);
    cudaGetSymbolAddress((void**)&ffh,  g_ffh);
    cudaGetSymbolAddress((void**)&x1,   g_x1);
    cudaGetSymbolAddress((void**)&x2,   g_x2);
    cudaGetSymbolAddress((void**)&bqkv, g_bqkv);
    cudaGetSymbolAddress((void**)&bkv,  g_bkv);

    cudaFuncSetAttribute(attn_h<true>,  cudaFuncAttributeMaxDynamicSharedMemorySize, ATTN_SMEM);
    cudaFuncSetAttribute(attn_h<false>, cudaFuncAttributeMaxDynamicSharedMemorySize, ATTN_SMEM);
    cudaFuncSetAttribute(gemm_h<false,false,true >, cudaFuncAttributeMaxDynamicSharedMemorySize, GEMM_SMEM);
    cudaFuncSetAttribute(gemm_h<false,true ,false>, cudaFuncAttributeMaxDynamicSharedMemorySize, GEMM_SMEM);
    cudaFuncSetAttribute(gemm_h<true ,false,true >, cudaFuncAttributeMaxDynamicSharedMemorySize, GEMM_SMEM);

    const long cvt_total = 8L*SEGP + 3L*MEGA + 1280;
    cvt_all<<<(unsigned)((cvt_total + 255)/256), 256>>>(
        sa_wq, sa_wk, sa_wv, sa_wo, ca_wq, ca_wk, ca_wv, ca_wo,
        ff_w1, ff_w2, enc, sa_bq, sa_bk, sa_bv, ca_bk, ca_bv,
        wh, ench, bqkv, bkv);

    const dim3 thr(256);
    const dim3 gQKV(3072/128, NTOK/128);
    const dim3 gKV (2048/128, NTOK/128);
    const dim3 gP  (EDIM/128, NTOK/128);
    const dim3 gF1 (FFD/128,  NTOK/128);
    const dim3 gA  (TSEQ/128, 16, 2);

    // ---- self attention ----
    ln_kernel<<<NTOK, 256>>>(x, ln1g, ln1b, hh);
    gemm_h<false,false,true ><<<gQKV, thr, GEMM_SMEM>>>(hh, wh, bqkv, nullptr, qkvh, 3072, 1024);
    attn_h<true><<<gA, thr, ATTN_SMEM>>>(qkvh, qkvh+1024, qkvh+2048, aoh, 3072, 3072);
    gemm_h<false,true ,false><<<gP, thr, GEMM_SMEM>>>(aoh, wh+(size_t)3*MEGA, sa_bo, x, x1, EDIM, EDIM);

    // ---- cross attention ----
    ln_kernel<<<NTOK, 256>>>(x1, ln2g, ln2b, hh);
    gemm_h<false,false,true ><<<gP,  thr, GEMM_SMEM>>>(hh,   wh+(size_t)4*MEGA, ca_bq, nullptr, qh,   EDIM, 1024);
    gemm_h<false,false,true ><<<gKV, thr, GEMM_SMEM>>>(ench, wh+(size_t)5*MEGA, bkv,   nullptr, qkvh, 2048, 1024);
    attn_h<false><<<gA, thr, ATTN_SMEM>>>(qh, qkvh, qkvh+1024, aoh, 1024, 2048);
    gemm_h<false,true ,false><<<gP, thr, GEMM_SMEM>>>(aoh, wh+(size_t)7*MEGA, ca_bo, x1, x2, EDIM, EDIM);

    // ---- feed-forward ----
    ln_kernel<<<NTOK, 256>>>(x2, ln3g, ln3b, hh);
    gemm_h<true ,false,true ><<<gF1, thr, GEMM_SMEM>>>(hh,  wh+(size_t)8*MEGA,  ff_b1, nullptr, ffh, FFD, 1024);
    gemm_h<false,true ,false><<<gP, thr, GEMM_SMEM>>>(ffh, wh+(size_t)12*MEGA, ff_b2, x2, out, EDIM, FFD);
}

// round 10
// speedup vs baseline: 4.0950x; 1.0146x over previous
#include <cuda_runtime.h>
#include <cuda_fp16.h>
#include <math.h>
#include <stdint.h>

#define EDIM 1024
#define TSEQ 2048
#define NTOK 4096
#define FFD  4096
#define LN_EPS 1e-5f
#define MEGA 1048576

__device__ __half g_wh  [(size_t)16*MEGA];
__device__ __half g_ench[(size_t)NTOK*EDIM];
__device__ __half g_hh  [(size_t)NTOK*EDIM];
__device__ __half g_qkvh[(size_t)12*MEGA];
__device__ __half g_qh  [(size_t)NTOK*EDIM];
__device__ __half g_aoh [(size_t)NTOK*EDIM];
__device__ __half g_ffh [(size_t)NTOK*FFD];
__device__ float  g_x1  [(size_t)NTOK*EDIM];
__device__ float  g_x2  [(size_t)NTOK*EDIM];
__device__ float  g_bqkv[3072];
__device__ float  g_bkv [2048];

// ---------------- primitives ----------------
__device__ __forceinline__ void mma_f16(float* c, const uint32_t* a, uint32_t b0, uint32_t b1){
    asm volatile("mma.sync.aligned.m16n8k16.row.col.f32.f16.f16.f32 "
        "{%0,%1,%2,%3}, {%4,%5,%6,%7}, {%8,%9}, {%0,%1,%2,%3};"
        : "+f"(c[0]), "+f"(c[1]), "+f"(c[2]), "+f"(c[3])
        : "r"(a[0]), "r"(a[1]), "r"(a[2]), "r"(a[3]), "r"(b0), "r"(b1));
}
__device__ __forceinline__ void ldsm4(uint32_t* r, uint32_t a){
    asm volatile("ldmatrix.sync.aligned.m8n8.x4.shared.b16 {%0,%1,%2,%3}, [%4];"
        : "=r"(r[0]), "=r"(r[1]), "=r"(r[2]), "=r"(r[3]) : "r"(a));
}
__device__ __forceinline__ void ldsm4t(uint32_t* r, uint32_t a){
    asm volatile("ldmatrix.sync.aligned.m8n8.x4.trans.shared.b16 {%0,%1,%2,%3}, [%4];"
        : "=r"(r[0]), "=r"(r[1]), "=r"(r[2]), "=r"(r[3]) : "r"(a));
}
__device__ __forceinline__ void cpa16(uint32_t dst, const void* src){
    asm volatile("cp.async.cg.shared.global [%0], [%1], 16;" :: "r"(dst), "l"(src));
}
#define CP_COMMIT() asm volatile("cp.async.commit_group;")
#define CP_WAIT(n)  asm volatile("cp.async.wait_group %0;" :: "n"(n))
__device__ __forceinline__ uint32_t pack2(float lo, float hi){
    __half2 h = __floats2half2_rn(lo, hi);
    return *(uint32_t*)&h;
}
__device__ __forceinline__ uint32_t pexp2(float lo, float hi){
    __half2 h = h2exp2(__floats2half2_rn(lo, hi));
    return *(uint32_t*)&h;
}
#define HONES 0x3C003C00u

// ---------------- mega convert ----------------
#define SEGP 262144
__global__ __launch_bounds__(256)
void cvt_all(const float* __restrict__ sa_wq, const float* __restrict__ sa_wk,
             const float* __restrict__ sa_wv, const float* __restrict__ sa_wo,
             const float* __restrict__ ca_wq, const float* __restrict__ ca_wk,
             const float* __restrict__ ca_wv, const float* __restrict__ ca_wo,
             const float* __restrict__ ff_w1, const float* __restrict__ ff_w2,
             const float* __restrict__ enc,
             const float* __restrict__ sa_bq, const float* __restrict__ sa_bk,
             const float* __restrict__ sa_bv,
             const float* __restrict__ ca_bk, const float* __restrict__ ca_bv,
             __half* __restrict__ wh, __half* __restrict__ ench,
             float* __restrict__ bqkv, float* __restrict__ bkv)
{
    const long i = (long)blockIdx.x*256 + threadIdx.x;
    if (i < 8L*SEGP){
        const int seg = (int)(i / SEGP);
        const int li  = (int)(i % SEGP);
        const float4 v = ((const float4*)(seg==0?sa_wq: seg==1?sa_wk: seg==2?sa_wv:
                          seg==3?sa_wo: seg==4?ca_wq: seg==5?ca_wk: seg==6?ca_wv:ca_wo))[li];
        uint2 o; o.x = pack2(v.x, v.y); o.y = pack2(v.z, v.w);
        size_t d;
        const int row = li >> 8, n = (li & 255) * 4;
        if (seg <= 2)       d = (size_t)row*3072 + seg*1024 + n;
        else if (seg == 3)  d = (size_t)3*MEGA + (size_t)li*4;
        else if (seg == 4)  d = (size_t)4*MEGA + (size_t)li*4;
        else if (seg <= 6)  d = (size_t)5*MEGA + (size_t)row*2048 + (seg-5)*1024 + n;
        else                d = (size_t)7*MEGA + (size_t)li*4;
        *(uint2*)&wh[d] = o;
        return;
    }
    long j = i - 8L*SEGP;
    if (j < (long)MEGA){
        const float4 v = ((const float4*)ff_w1)[j];
        uint2 o; o.x = pack2(v.x,v.y); o.y = pack2(v.z,v.w);
        *(uint2*)&wh[(size_t)8*MEGA + (size_t)j*4] = o;
        return;
    }
    j -= MEGA;
    if (j < (long)MEGA){
        const float4 v = ((const float4*)ff_w2)[j];
        uint2 o; o.x = pack2(v.x,v.y); o.y = pack2(v.z,v.w);
        *(uint2*)&wh[(size_t)12*MEGA + (size_t)j*4] = o;
        return;
    }
    j -= MEGA;
    if (j < (long)MEGA){
        const float4 v = ((const float4*)enc)[j];
        uint2 o; o.x = pack2(v.x,v.y); o.y = pack2(v.z,v.w);
        *(uint2*)&ench[(size_t)j*4] = o;
        return;
    }
    j -= MEGA;
    if (j < 768){
        const int e = (int)j * 4;
        const int sub = e >> 10, idx = e & 1023;
        const float4 v = *(const float4*)&((sub==0?sa_bq: sub==1?sa_bk:sa_bv)[idx]);
        *(float4*)&bqkv[e] = v;
        return;
    }
    j -= 768;
    if (j < 512){
        const int e = (int)j * 4;
        const int sub = e >> 10, idx = e & 1023;
        const float4 v = *(const float4*)&((sub==0?ca_bk:ca_bv)[idx]);
        *(float4*)&bkv[e] = v;
    }
}

// ---------------- LayerNorm (fp32 in, half out) ----------------
__global__ __launch_bounds__(256)
void ln_kernel(const float* __restrict__ x, const float* __restrict__ gamma,
               const float* __restrict__ beta, __half* __restrict__ out)
{
    const int row = blockIdx.x;
    const int t = threadIdx.x;
    const float4 v = ((const float4*)(x + (size_t)row*EDIM))[t];
    float s  = v.x + v.y + v.z + v.w;
    float ss = v.x*v.x + v.y*v.y + v.z*v.z + v.w*v.w;
#pragma unroll
    for (int o = 16; o; o >>= 1){
        s  += __shfl_xor_sync(0xffffffffu, s,  o);
        ss += __shfl_xor_sync(0xffffffffu, ss, o);
    }
    __shared__ float sh_s[8], sh_ss[8];
    const int w = t >> 5, l = t & 31;
    if (l == 0){ sh_s[w] = s; sh_ss[w] = ss; }
    __syncthreads();
    if (w == 0){
        s  = (l < 8) ? sh_s[l]  : 0.f;
        ss = (l < 8) ? sh_ss[l] : 0.f;
#pragma unroll
        for (int o = 4; o; o >>= 1){
            s  += __shfl_xor_sync(0xffffffffu, s,  o);
            ss += __shfl_xor_sync(0xffffffffu, ss, o);
        }
        if (l == 0){ sh_s[0] = s; sh_ss[0] = ss; }
    }
    __syncthreads();
    const float mu   = sh_s[0] * (1.f/EDIM);
    const float var  = sh_ss[0] * (1.f/EDIM) - mu*mu;
    const float rstd = rsqrtf(var + LN_EPS);
    const float4 g4 = ((const float4*)gamma)[t];
    const float4 b4 = ((const float4*)beta)[t];
    __half2* orow = (__half2*)(out + (size_t)row*EDIM);
    orow[2*t]   = __floats2half2_rn((v.x-mu)*rstd*g4.x + b4.x, (v.y-mu)*rstd*g4.y + b4.y);
    orow[2*t+1] = __floats2half2_rn((v.z-mu)*rstd*g4.z + b4.z, (v.w-mu)*rstd*g4.w + b4.w);
}

// ---------------- FP16 GEMM, BK=64, 3-stage cp.async + ldmatrix ----------
#define ASTG 9216            // 128 rows x 72 halves
#define BSTG 8704            // 64 rows x 136 halves
#define GEMM_SMEM ((3*(ASTG + BSTG))*2)   // 107520 B
template<bool RELU, bool RES, bool OUTH>
__global__ __launch_bounds__(256,2)
void gemm_h(const __half* __restrict__ A, const __half* __restrict__ W,
            const float* __restrict__ bias, const float* __restrict__ res,
            void* __restrict__ Cv, int N, int K)
{
    extern __shared__ __half gsm[];
    __half* As = gsm;               // 3 x ASTG
    __half* Bs = gsm + 3*ASTG;      // 3 x BSTG

    const int tid  = threadIdx.x;
    const int lane = tid & 31;
    const int wid  = tid >> 5;
    const int gid  = lane >> 2;
    const int tig  = lane & 3;
    const int wm   = (wid & 3) * 32;
    const int wn   = (wid >> 2) * 64;
    const int m0 = blockIdx.y * 128;
    const int n0 = blockIdx.x * 128;

    const uint32_t asb = (uint32_t)__cvta_generic_to_shared(As);
    const uint32_t bsb = (uint32_t)__cvta_generic_to_shared(Bs);

    const int a_r = wm + (lane&7) + ((lane>>3)&1)*8;   // +ma*16
    const int a_k = ((lane>>4)&1)*8;                   // +kc*16
    const int b_k = (lane&7) + ((lane>>3)&1)*8;        // +kc*16
    const int b_n = wn + ((lane>>4)&1)*8;              // +np*16

    float acc[2][8][4];
#pragma unroll
    for (int i=0;i<2;i++)
#pragma unroll
        for (int j=0;j<8;j++)
#pragma unroll
            for (int k=0;k<4;k++) acc[i][j][k]=0.f;

#define LOADSTAGE(b_, kt_) do{                                               \
        _Pragma("unroll")                                                    \
        for (int i=0;i<4;i++){                                               \
            int idx = tid + 256*i;                                           \
            int ar = idx>>3, ac = (idx&7)*8;                                 \
            cpa16(asb + (uint32_t)(((b_)*ASTG + ar*72 + ac)*2),              \
                  A + (size_t)(m0+ar)*K + (kt_)*64 + ac);                    \
        }                                                                    \
        _Pragma("unroll")                                                    \
        for (int i=0;i<4;i++){                                               \
            int idx = tid + 256*i;                                           \
            int kr = idx>>4, nc = (idx&15)*8;                                \
            cpa16(bsb + (uint32_t)(((b_)*BSTG + kr*136 + nc)*2),             \
                  W + (size_t)((kt_)*64+kr)*N + n0 + nc);                    \
        }                                                                    \
        CP_COMMIT();                                                         \
    }while(0)

    LOADSTAGE(0, 0);
    LOADSTAGE(1, 1);
    const int KT = K >> 6;
    for (int kt = 0; kt < KT; ++kt){
        CP_WAIT(1);
        __syncthreads();
        if (kt + 2 < KT) LOADSTAGE((kt+2)%3, kt+2);
        else CP_COMMIT();
        const int buf = kt % 3;
        const uint32_t asb_b = asb + (uint32_t)(buf*ASTG*2);
        const uint32_t bsb_b = bsb + (uint32_t)(buf*BSTG*2);
#pragma unroll
        for (int kc = 0; kc < 4; kc++){
            uint32_t af[2][4];
#pragma unroll
            for (int ma = 0; ma < 2; ma++)
                ldsm4(af[ma], asb_b + (uint32_t)(((a_r + ma*16)*72 + a_k + kc*16)*2));
#pragma unroll
            for (int np = 0; np < 4; np++){
                uint32_t bf[4];
                ldsm4t(bf, bsb_b + (uint32_t)(((b_k + kc*16)*136 + b_n + np*16)*2));
                mma_f16(acc[0][2*np  ], af[0], bf[0], bf[1]);
                mma_f16(acc[0][2*np+1], af[0], bf[2], bf[3]);
                mma_f16(acc[1][2*np  ], af[1], bf[0], bf[1]);
                mma_f16(acc[1][2*np+1], af[1], bf[2], bf[3]);
            }
        }
    }
#undef LOADSTAGE

#pragma unroll
    for (int ma = 0; ma < 2; ma++){
        const int r0 = m0 + wm + ma*16 + gid;
        const int r1 = r0 + 8;
#pragma unroll
        for (int na = 0; na < 8; na++){
            const int c = n0 + wn + na*8 + 2*tig;
            const float2 bb = *(const float2*)&bias[c];
            float v00 = acc[ma][na][0] + bb.x;
            float v01 = acc[ma][na][1] + bb.y;
            float v10 = acc[ma][na][2] + bb.x;
            float v11 = acc[ma][na][3] + bb.y;
            if (RELU){
                v00 = fmaxf(v00,0.f); v01 = fmaxf(v01,0.f);
                v10 = fmaxf(v10,0.f); v11 = fmaxf(v11,0.f);
            }
            if (RES){
                const float2 q0 = *(const float2*)&res[(size_t)r0*N + c];
                const float2 q1 = *(const float2*)&res[(size_t)r1*N + c];
                v00 += q0.x; v01 += q0.y; v10 += q1.x; v11 += q1.y;
            }
            if (OUTH){
                __half* Ch = (__half*)Cv;
                *(__half2*)&Ch[(size_t)r0*N + c] = __floats2half2_rn(v00, v01);
                *(__half2*)&Ch[(size_t)r1*N + c] = __floats2half2_rn(v10, v11);
            } else {
                float* Cf = (float*)Cv;
                float2 o0; o0.x=v00; o0.y=v01;
                float2 o1; o1.x=v10; o1.y=v11;
                *(float2*)&Cf[(size_t)r0*N + c] = o0;
                *(float2*)&Cf[(size_t)r1*N + c] = o1;
            }
        }
    }
}

// ---------------- Flash attention fp16, log2-domain softmax (unchanged R9) ----
#define ATP 72
#define KVB (64*ATP)
#define ATTN_SMEM ((128*ATP + 4*KVB)*2)
template<bool CAUSAL>
__global__ __launch_bounds__(256,2)
void attn_h(const __half* __restrict__ Qg, const __half* __restrict__ Kg,
            const __half* __restrict__ Vg, __half* __restrict__ Og,
            int ldq, int ldkv)
{
    extern __shared__ __half smh[];
    __half* Qs = smh;
    __half* Ks = Qs + 128*ATP;
    __half* Vs = Ks + 2*KVB;

    const int tid  = threadIdx.x;
    const int lane = tid & 31;
    const int wid  = tid >> 5;
    const int gid  = lane >> 2;
    const int tig  = lane & 3;
    const int wm   = wid * 16;
    const int qb = CAUSAL ? ((int)gridDim.x - 1 - (int)blockIdx.x) : (int)blockIdx.x;
    const int h = blockIdx.y, b = blockIdx.z;
    const size_t baseq = (size_t)b*TSEQ*ldq  + (size_t)h*64;
    const size_t basek = (size_t)b*TSEQ*ldkv + (size_t)h*64;
    const size_t baseo = (size_t)b*TSEQ*EDIM + (size_t)h*64;

    const uint32_t qsb = (uint32_t)__cvta_generic_to_shared(Qs);
    const uint32_t ksb = (uint32_t)__cvta_generic_to_shared(Ks);
    const uint32_t vsb = (uint32_t)__cvta_generic_to_shared(Vs);

#pragma unroll
    for (int i = 0; i < 4; i++){
        int idx = tid + 256*i;
        int r = idx>>3, c = (idx&7)*8;
        cpa16(qsb + (uint32_t)((r*ATP + c)*2), Qg + baseq + (size_t)(qb*128 + r)*ldq + c);
    }
    CP_COMMIT();
#define LOADKV(b_, kt_) do{                                                   \
        _Pragma("unroll")                                                     \
        for (int i = 0; i < 2; i++){                                          \
            int idx = tid + 256*i;                                            \
            int r = idx>>3, c = (idx&7)*8;                                    \
            size_t go = basek + (size_t)((kt_)*64 + r)*ldkv + c;              \
            uint32_t so = (uint32_t)(((b_)*KVB + r*ATP + c)*2);               \
            cpa16(ksb + so, Kg + go);                                         \
            cpa16(vsb + so, Vg + go);                                         \
        }                                                                     \
        CP_COMMIT();                                                          \
    }while(0)
    LOADKV(0, 0);
    CP_WAIT(1);
    __syncthreads();

    const int q_r = wm + (lane&7) + ((lane>>3)&1)*8;
    const int q_k = ((lane>>4)&1)*8;
    uint32_t qf[4][4];
#pragma unroll
    for (int kc = 0; kc < 4; kc++)
        ldsm4(qf[kc], qsb + (uint32_t)((q_r*ATP + q_k + kc*16)*2));

    const int k_r = (lane&7);
    const int k_c = (lane>>3)*8;
    const int v_r = (lane&7) + ((lane>>3)&1)*8;
    const int v_n = ((lane>>4)&1)*8;

    float oacc[8][4];
#pragma unroll
    for (int i=0;i<8;i++)
#pragma unroll
        for (int j=0;j<4;j++) oacc[i][j]=0.f;
    float m0=-1e30f, m1=-1e30f, l0=0.f, l1=0.f;

    const int nkt = CAUSAL ? (2*qb + 2) : (TSEQ/64);
    const int gr0 = qb*128 + wm + gid;
    const int gr1 = gr0 + 8;
    const float SC = 0.125f * 1.44269504f;

    for (int kt = 0; kt < nkt; ++kt){
        CP_WAIT(0);
        __syncthreads();
        const int buf = kt & 1;
        if (kt + 1 < nkt) LOADKV(buf^1, kt+1);
        const uint32_t ksb_b = ksb + (uint32_t)(buf*KVB*2);
        const uint32_t vsb_b = vsb + (uint32_t)(buf*KVB*2);

        float sa[8][4];
#pragma unroll
        for (int na=0;na<8;na++)
#pragma unroll
            for (int e=0;e<4;e++) sa[na][e]=0.f;
#pragma unroll
        for (int na = 0; na < 8; na++){
#pragma unroll
            for (int kq = 0; kq < 2; kq++){
                uint32_t kf[4];
                ldsm4(kf, ksb_b + (uint32_t)(((na*8 + k_r)*ATP + kq*32 + k_c)*2));
                mma_f16(sa[na], qf[2*kq  ], kf[0], kf[1]);
                mma_f16(sa[na], qf[2*kq+1], kf[2], kf[3]);
            }
        }
#pragma unroll
        for (int na = 0; na < 8; na++)
#pragma unroll
            for (int e = 0; e < 4; e++) sa[na][e] *= SC;
        if (CAUSAL && kt >= 2*qb){
#pragma unroll
            for (int na = 0; na < 8; na++){
                const int c0 = kt*64 + na*8 + 2*tig;
#pragma unroll
                for (int e = 0; e < 4; e++){
                    const int col = c0 + (e&1);
                    const int row = (e<2) ? gr0 : gr1;
                    if (col > row) sa[na][e] = -1e30f;
                }
            }
        }
        float mx0=-1e30f, mx1=-1e30f;
#pragma unroll
        for (int na=0;na<8;na++){
            mx0 = fmaxf(mx0, fmaxf(sa[na][0], sa[na][1]));
            mx1 = fmaxf(mx1, fmaxf(sa[na][2], sa[na][3]));
        }
        mx0 = fmaxf(mx0, __shfl_xor_sync(0xffffffffu, mx0, 1));
        mx0 = fmaxf(mx0, __shfl_xor_sync(0xffffffffu, mx0, 2));
        mx1 = fmaxf(mx1, __shfl_xor_sync(0xffffffffu, mx1, 1));
        mx1 = fmaxf(mx1, __shfl_xor_sync(0xffffffffu, mx1, 2));
        const float mn0 = fmaxf(m0, mx0);
        const float mn1 = fmaxf(m1, mx1);
        const float al0 = exp2f(m0 - mn0);
        const float al1 = exp2f(m1 - mn1);
        m0 = mn0; m1 = mn1;
        uint32_t pf[4][4];
#pragma unroll
        for (int kc = 0; kc < 4; kc++){
            pf[kc][0] = pexp2(sa[2*kc  ][0]-mn0, sa[2*kc  ][1]-mn0);
            pf[kc][1] = pexp2(sa[2*kc  ][2]-mn1, sa[2*kc  ][3]-mn1);
            pf[kc][2] = pexp2(sa[2*kc+1][0]-mn0, sa[2*kc+1][1]-mn0);
            pf[kc][3] = pexp2(sa[2*kc+1][2]-mn1, sa[2*kc+1][3]-mn1);
        }
        float lacc[4] = {0.f, 0.f, 0.f, 0.f};
#pragma unroll
        for (int kc = 0; kc < 4; kc++)
            mma_f16(lacc, pf[kc], HONES, HONES);
        l0 = l0*al0 + lacc[0];
        l1 = l1*al1 + lacc[2];
#pragma unroll
        for (int na=0;na<8;na++){
            oacc[na][0]*=al0; oacc[na][1]*=al0;
            oacc[na][2]*=al1; oacc[na][3]*=al1;
        }
#pragma unroll
        for (int kc = 0; kc < 4; kc++){
#pragma unroll
            for (int np = 0; np < 4; np++){
                uint32_t vf[4];
                ldsm4t(vf, vsb_b + (uint32_t)(((kc*16 + v_r)*ATP + v_n + np*16)*2));
                mma_f16(oacc[2*np  ], pf[kc], vf[0], vf[1]);
                mma_f16(oacc[2*np+1], pf[kc], vf[2], vf[3]);
            }
        }
    }
#undef LOADKV

    const float li0 = 1.f / l0;
    const float li1 = 1.f / l1;
#pragma unroll
    for (int na = 0; na < 8; na++){
        const int c = na*8 + 2*tig;
        *(__half2*)&Og[baseo + (size_t)gr0*EDIM + c] =
            __floats2half2_rn(oacc[na][0]*li0, oacc[na][1]*li0);
        *(__half2*)&Og[baseo + (size_t)gr1*EDIM + c] =
            __floats2half2_rn(oacc[na][2]*li1, oacc[na][3]*li1);
    }
}

// ---------------- launch ----------------
extern "C" void kernel_launch(void* const* d_in, const int* in_sizes, int n_in,
                              void* d_out, int out_size)
{
    const float* x     = (const float*)d_in[0];
    const float* enc   = (const float*)d_in[1];
    const float* sa_wq = (const float*)d_in[3];  const float* sa_bq = (const float*)d_in[4];
    const float* sa_wk = (const float*)d_in[5];  const float* sa_bk = (const float*)d_in[6];
    const float* sa_wv = (const float*)d_in[7];  const float* sa_bv = (const float*)d_in[8];
    const float* sa_wo = (const float*)d_in[9];  const float* sa_bo = (const float*)d_in[10];
    const float* ca_wq = (const float*)d_in[11]; const float* ca_bq = (const float*)d_in[12];
    const float* ca_wk = (const float*)d_in[13]; const float* ca_bk = (const float*)d_in[14];
    const float* ca_wv = (const float*)d_in[15]; const float* ca_bv = (const float*)d_in[16];
    const float* ca_wo = (const float*)d_in[17]; const float* ca_bo = (const float*)d_in[18];
    const float* ff_w1 = (const float*)d_in[19]; const float* ff_b1 = (const float*)d_in[20];
    const float* ff_w2 = (const float*)d_in[21]; const float* ff_b2 = (const float*)d_in[22];
    const float* ln1g  = (const float*)d_in[23]; const float* ln1b  = (const float*)d_in[24];
    const float* ln2g  = (const float*)d_in[25]; const float* ln2b  = (const float*)d_in[26];
    const float* ln3g  = (const float*)d_in[27]; const float* ln3b  = (const float*)d_in[28];
    float* out = (float*)d_out;

    __half *wh, *ench, *hh, *qkvh, *qh, *aoh, *ffh;
    float *x1, *x2, *bqkv, *bkv;
    cudaGetSymbolAddress((void**)&wh,   g_wh);
    cudaGetSymbolAddress((void**)&ench, g_ench);
    cudaGetSymbolAddress((void**)&hh,   g_hh);
    cudaGetSymbolAddress((void**)&qkvh, g_qkvh);
    cudaGetSymbolAddress((void**)&qh,   g_qh);
    cudaGetSymbolAddress((void**)&aoh,  g_aoh);
    cudaGetSymbolAddress((void**)&ffh,  g_ffh);
    cudaGetSymbolAddress((void**)&x1,   g_x1);
    cudaGetSymbolAddress((void**)&x2,   g_x2);
    cudaGetSymbolAddress((void**)&bqkv, g_bqkv);
    cudaGetSymbolAddress((void**)&bkv,  g_bkv);

    cudaFuncSetAttribute(attn_h<true>,  cudaFuncAttributeMaxDynamicSharedMemorySize, ATTN_SMEM);
    cudaFuncSetAttribute(attn_h<false>, cudaFuncAttributeMaxDynamicSharedMemorySize, ATTN_SMEM);
    cudaFuncSetAttribute(gemm_h<false,false,true >, cudaFuncAttributeMaxDynamicSharedMemorySize, GEMM_SMEM);
    cudaFuncSetAttribute(gemm_h<false,true ,false>, cudaFuncAttributeMaxDynamicSharedMemorySize, GEMM_SMEM);
    cudaFuncSetAttribute(gemm_h<true ,false,true >, cudaFuncAttributeMaxDynamicSharedMemorySize, GEMM_SMEM);

    const long cvt_total = 8L*SEGP + 3L*MEGA + 1280;
    cvt_all<<<(unsigned)((cvt_total + 255)/256), 256>>>(
        sa_wq, sa_wk, sa_wv, sa_wo, ca_wq, ca_wk, ca_wv, ca_wo,
        ff_w1, ff_w2, enc, sa_bq, sa_bk, sa_bv, ca_bk, ca_bv,
        wh, ench, bqkv, bkv);

    const dim3 thr(256);
    const dim3 gQKV(3072/128, NTOK/128);
    const dim3 gKV (2048/128, NTOK/128);
    const dim3 gP  (EDIM/128, NTOK/128);
    const dim3 gF1 (FFD/128,  NTOK/128);
    const dim3 gA  (TSEQ/128, 16, 2);

    // ---- self attention ----
    ln_kernel<<<NTOK, 256>>>(x, ln1g, ln1b, hh);
    gemm_h<false,false,true ><<<gQKV, thr, GEMM_SMEM>>>(hh, wh, bqkv, nullptr, qkvh, 3072, 1024);
    attn_h<true><<<gA, thr, ATTN_SMEM>>>(qkvh, qkvh+1024, qkvh+2048, aoh, 3072, 3072);
    gemm_h<false,true ,false><<<gP, thr, GEMM_SMEM>>>(aoh, wh+(size_t)3*MEGA, sa_bo, x, x1, EDIM, EDIM);

    // ---- cross attention ----
    ln_kernel<<<NTOK, 256>>>(x1, ln2g, ln2b, hh);
    gemm_h<false,false,true ><<<gP,  thr, GEMM_SMEM>>>(hh,   wh+(size_t)4*MEGA, ca_bq, nullptr, qh,   EDIM, 1024);
    gemm_h<false,false,true ><<<gKV, thr, GEMM_SMEM>>>(ench, wh+(size_t)5*MEGA, bkv,   nullptr, qkvh, 2048, 1024);
    attn_h<false><<<gA, thr, ATTN_SMEM>>>(qh, qkvh, qkvh+1024, aoh, 1024, 2048);
    gemm_h<false,true ,false><<<gP, thr, GEMM_SMEM>>>(aoh, wh+(size_t)7*MEGA, ca_bo, x1, x2, EDIM, EDIM);

    // ---- feed-forward ----
    ln_kernel<<<NTOK, 256>>>(x2, ln3g, ln3b, hh);
    gemm_h<true ,false,true ><<<gF1, thr, GEMM_SMEM>>>(hh,  wh+(size_t)8*MEGA,  ff_b1, nullptr, ffh, FFD, 1024);
    gemm_h<false,true ,false><<<gP, thr, GEMM_SMEM>>>(ffh, wh+(size_t)12*MEGA, ff_b2, x2, out, EDIM, FFD);
}

// round 13
// speedup vs baseline: 4.1691x; 1.0181x over previous
#include <cuda_runtime.h>
#include <cuda_fp16.h>
#include <math.h>
#include <stdint.h>

#define EDIM 1024
#define TSEQ 2048
#define NTOK 4096
#define FFD  4096
#define LN_EPS 1e-5f
#define MEGA 1048576
#define QSCALE 0.18033688f   /* 0.125 * log2(e) */

__device__ __half g_wh  [(size_t)16*MEGA];
__device__ __half g_ench[(size_t)NTOK*EDIM];
__device__ __half g_hh  [(size_t)NTOK*EDIM];
__device__ __half g_qkvh[(size_t)12*MEGA];
__device__ __half g_qh  [(size_t)NTOK*EDIM];
__device__ __half g_aoh [(size_t)NTOK*EDIM];
__device__ __half g_ffh [(size_t)NTOK*FFD];
__device__ float  g_x1  [(size_t)NTOK*EDIM];
__device__ float  g_x2  [(size_t)NTOK*EDIM];
__device__ float  g_bqkv[3072];
__device__ float  g_bkv [2048];
__device__ float  g_bqc [1024];

// ---------------- primitives ----------------
__device__ __forceinline__ void mma_f16(float* c, const uint32_t* a, uint32_t b0, uint32_t b1){
    asm volatile("mma.sync.aligned.m16n8k16.row.col.f32.f16.f16.f32 "
        "{%0,%1,%2,%3}, {%4,%5,%6,%7}, {%8,%9}, {%0,%1,%2,%3};"
        : "+f"(c[0]), "+f"(c[1]), "+f"(c[2]), "+f"(c[3])
        : "r"(a[0]), "r"(a[1]), "r"(a[2]), "r"(a[3]), "r"(b0), "r"(b1));
}
__device__ __forceinline__ void ldsm4(uint32_t* r, uint32_t a){
    asm volatile("ldmatrix.sync.aligned.m8n8.x4.shared.b16 {%0,%1,%2,%3}, [%4];"
        : "=r"(r[0]), "=r"(r[1]), "=r"(r[2]), "=r"(r[3]) : "r"(a));
}
__device__ __forceinline__ void ldsm4t(uint32_t* r, uint32_t a){
    asm volatile("ldmatrix.sync.aligned.m8n8.x4.trans.shared.b16 {%0,%1,%2,%3}, [%4];"
        : "=r"(r[0]), "=r"(r[1]), "=r"(r[2]), "=r"(r[3]) : "r"(a));
}
__device__ __forceinline__ void cpa16(uint32_t dst, const void* src){
    asm volatile("cp.async.cg.shared.global [%0], [%1], 16;" :: "r"(dst), "l"(src));
}
#define CP_COMMIT() asm volatile("cp.async.commit_group;")
#define CP_WAIT(n)  asm volatile("cp.async.wait_group %0;" :: "n"(n))
__device__ __forceinline__ uint32_t pack2(float lo, float hi){
    __half2 h = __floats2half2_rn(lo, hi);
    return *(uint32_t*)&h;
}
__device__ __forceinline__ uint32_t pexp2(float lo, float hi){
    __half2 h = h2exp2(__floats2half2_rn(lo, hi));
    return *(uint32_t*)&h;
}
#define HONES 0x3C003C00u

// ---------------- mega convert (Q weights/biases pre-scaled by QSCALE) -------
#define SEGP 262144
__global__ __launch_bounds__(256)
void cvt_all(const float* __restrict__ sa_wq, const float* __restrict__ sa_wk,
             const float* __restrict__ sa_wv, const float* __restrict__ sa_wo,
             const float* __restrict__ ca_wq, const float* __restrict__ ca_wk,
             const float* __restrict__ ca_wv, const float* __restrict__ ca_wo,
             const float* __restrict__ ff_w1, const float* __restrict__ ff_w2,
             const float* __restrict__ enc,
             const float* __restrict__ sa_bq, const float* __restrict__ sa_bk,
             const float* __restrict__ sa_bv,
             const float* __restrict__ ca_bq,
             const float* __restrict__ ca_bk, const float* __restrict__ ca_bv,
             __half* __restrict__ wh, __half* __restrict__ ench,
             float* __restrict__ bqkv, float* __restrict__ bkv,
             float* __restrict__ bqc)
{
    const long i = (long)blockIdx.x*256 + threadIdx.x;
    if (i < 8L*SEGP){
        const int seg = (int)(i / SEGP);
        const int li  = (int)(i % SEGP);
        float4 v = ((const float4*)(seg==0?sa_wq: seg==1?sa_wk: seg==2?sa_wv:
                     seg==3?sa_wo: seg==4?ca_wq: seg==5?ca_wk: seg==6?ca_wv:ca_wo))[li];
        if (seg == 0 || seg == 4){
            v.x *= QSCALE; v.y *= QSCALE; v.z *= QSCALE; v.w *= QSCALE;
        }
        uint2 o; o.x = pack2(v.x, v.y); o.y = pack2(v.z, v.w);
        size_t d;
        const int row = li >> 8, n = (li & 255) * 4;
        if (seg <= 2)       d = (size_t)row*3072 + seg*1024 + n;
        else if (seg == 3)  d = (size_t)3*MEGA + (size_t)li*4;
        else if (seg == 4)  d = (size_t)4*MEGA + (size_t)li*4;
        else if (seg <= 6)  d = (size_t)5*MEGA + (size_t)row*2048 + (seg-5)*1024 + n;
        else                d = (size_t)7*MEGA + (size_t)li*4;
        *(uint2*)&wh[d] = o;
        return;
    }
    long j = i - 8L*SEGP;
    if (j < (long)MEGA){
        const float4 v = ((const float4*)ff_w1)[j];
        uint2 o; o.x = pack2(v.x,v.y); o.y = pack2(v.z,v.w);
        *(uint2*)&wh[(size_t)8*MEGA + (size_t)j*4] = o;
        return;
    }
    j -= MEGA;
    if (j < (long)MEGA){
        const float4 v = ((const float4*)ff_w2)[j];
        uint2 o; o.x = pack2(v.x,v.y); o.y = pack2(v.z,v.w);
        *(uint2*)&wh[(size_t)12*MEGA + (size_t)j*4] = o;
        return;
    }
    j -= MEGA;
    if (j < (long)MEGA){
        const float4 v = ((const float4*)enc)[j];
        uint2 o; o.x = pack2(v.x,v.y); o.y = pack2(v.z,v.w);
        *(uint2*)&ench[(size_t)j*4] = o;
        return;
    }
    j -= MEGA;
    if (j < 768){
        const int e = (int)j * 4;
        const int sub = e >> 10, idx = e & 1023;
        float4 v = *(const float4*)&((sub==0?sa_bq: sub==1?sa_bk:sa_bv)[idx]);
        if (sub == 0){ v.x*=QSCALE; v.y*=QSCALE; v.z*=QSCALE; v.w*=QSCALE; }
        *(float4*)&bqkv[e] = v;
        return;
    }
    j -= 768;
    if (j < 512){
        const int e = (int)j * 4;
        const int sub = e >> 10, idx = e & 1023;
        *(float4*)&bkv[e] = *(const float4*)&((sub==0?ca_bk:ca_bv)[idx]);
        return;
    }
    j -= 512;
    if (j < 256){
        const int e = (int)j * 4;
        float4 v = *(const float4*)&ca_bq[e];
        v.x*=QSCALE; v.y*=QSCALE; v.z*=QSCALE; v.w*=QSCALE;
        *(float4*)&bqc[e] = v;
    }
}

// ---------------- LayerNorm (fp32 in, half out) ----------------
__global__ __launch_bounds__(256)
void ln_kernel(const float* __restrict__ x, const float* __restrict__ gamma,
               const float* __restrict__ beta, __half* __restrict__ out)
{
    const int row = blockIdx.x;
    const int t = threadIdx.x;
    const float4 v = ((const float4*)(x + (size_t)row*EDIM))[t];
    float s  = v.x + v.y + v.z + v.w;
    float ss = v.x*v.x + v.y*v.y + v.z*v.z + v.w*v.w;
#pragma unroll
    for (int o = 16; o; o >>= 1){
        s  += __shfl_xor_sync(0xffffffffu, s,  o);
        ss += __shfl_xor_sync(0xffffffffu, ss, o);
    }
    __shared__ float sh_s[8], sh_ss[8];
    const int w = t >> 5, l = t & 31;
    if (l == 0){ sh_s[w] = s; sh_ss[w] = ss; }
    __syncthreads();
    if (w == 0){
        s  = (l < 8) ? sh_s[l]  : 0.f;
        ss = (l < 8) ? sh_ss[l] : 0.f;
#pragma unroll
        for (int o = 4; o; o >>= 1){
            s  += __shfl_xor_sync(0xffffffffu, s,  o);
            ss += __shfl_xor_sync(0xffffffffu, ss, o);
        }
        if (l == 0){ sh_s[0] = s; sh_ss[0] = ss; }
    }
    __syncthreads();
    const float mu   = sh_s[0] * (1.f/EDIM);
    const float var  = sh_ss[0] * (1.f/EDIM) - mu*mu;
    const float rstd = rsqrtf(var + LN_EPS);
    const float4 g4 = ((const float4*)gamma)[t];
    const float4 b4 = ((const float4*)beta)[t];
    __half2* orow = (__half2*)(out + (size_t)row*EDIM);
    orow[2*t]   = __floats2half2_rn((v.x-mu)*rstd*g4.x + b4.x, (v.y-mu)*rstd*g4.y + b4.y);
    orow[2*t+1] = __floats2half2_rn((v.z-mu)*rstd*g4.z + b4.z, (v.w-mu)*rstd*g4.w + b4.w);
}

// ---------------- FP16 GEMM body, BK=64, 3-stage cp.async + ldmatrix ----------
#define ASTG 9216            // 128 rows x 72 halves
#define BSTG 8704            // 64 rows x 136 halves
#define GEMM_SMEM ((3*(ASTG + BSTG))*2)   // 107520 B
template<bool RELU, bool RES, bool OUTH>
__device__ __forceinline__
void gemm_body(const __half* __restrict__ A, const __half* __restrict__ W,
               const float* __restrict__ bias, const float* __restrict__ res,
               void* __restrict__ Cv, int N, int K, int m0, int n0)
{
    extern __shared__ __half gsm[];
    __half* As = gsm;
    __half* Bs = gsm + 3*ASTG;

    const int tid  = threadIdx.x;
    const int lane = tid & 31;
    const int wid  = tid >> 5;
    const int gid  = lane >> 2;
    const int tig  = lane & 3;
    const int wm   = (wid & 3) * 32;
    const int wn   = (wid >> 2) * 64;

    const uint32_t asb = (uint32_t)__cvta_generic_to_shared(As);
    const uint32_t bsb = (uint32_t)__cvta_generic_to_shared(Bs);

    const int a_r = wm + (lane&7) + ((lane>>3)&1)*8;
    const int a_k = ((lane>>4)&1)*8;
    const int b_k = (lane&7) + ((lane>>3)&1)*8;
    const int b_n = wn + ((lane>>4)&1)*8;

    float acc[2][8][4];
#pragma unroll
    for (int i=0;i<2;i++)
#pragma unroll
        for (int j=0;j<8;j++)
#pragma unroll
            for (int k=0;k<4;k++) acc[i][j][k]=0.f;

#define LOADSTAGE(b_, kt_) do{                                               \
        _Pragma("unroll")                                                    \
        for (int i=0;i<4;i++){                                               \
            int idx = tid + 256*i;                                           \
            int ar = idx>>3, ac = (idx&7)*8;                                 \
            cpa16(asb + (uint32_t)(((b_)*ASTG + ar*72 + ac)*2),              \
                  A + (size_t)(m0+ar)*K + (kt_)*64 + ac);                    \
        }                                                                    \
        _Pragma("unroll")                                                    \
        for (int i=0;i<4;i++){                                               \
            int idx = tid + 256*i;                                           \
            int kr = idx>>4, nc = (idx&15)*8;                                \
            cpa16(bsb + (uint32_t)(((b_)*BSTG + kr*136 + nc)*2),             \
                  W + (size_t)((kt_)*64+kr)*N + n0 + nc);                    \
        }                                                                    \
        CP_COMMIT();                                                         \
    }while(0)

    LOADSTAGE(0, 0);
    LOADSTAGE(1, 1);
    const int KT = K >> 6;
    for (int kt = 0; kt < KT; ++kt){
        CP_WAIT(1);
        __syncthreads();
        if (kt + 2 < KT) LOADSTAGE((kt+2)%3, kt+2);
        else CP_COMMIT();
        const int buf = kt % 3;
        const uint32_t asb_b = asb + (uint32_t)(buf*ASTG*2);
        const uint32_t bsb_b = bsb + (uint32_t)(buf*BSTG*2);
#pragma unroll
        for (int kc = 0; kc < 4; kc++){
            uint32_t af[2][4];
#pragma unroll
            for (int ma = 0; ma < 2; ma++)
                ldsm4(af[ma], asb_b + (uint32_t)(((a_r + ma*16)*72 + a_k + kc*16)*2));
#pragma unroll
            for (int np = 0; np < 4; np++){
                uint32_t bf[4];
                ldsm4t(bf, bsb_b + (uint32_t)(((b_k + kc*16)*136 + b_n + np*16)*2));
                mma_f16(acc[0][2*np  ], af[0], bf[0], bf[1]);
                mma_f16(acc[0][2*np+1], af[0], bf[2], bf[3]);
                mma_f16(acc[1][2*np  ], af[1], bf[0], bf[1]);
                mma_f16(acc[1][2*np+1], af[1], bf[2], bf[3]);
            }
        }
    }
#undef LOADSTAGE

#pragma unroll
    for (int ma = 0; ma < 2; ma++){
        const int r0 = m0 + wm + ma*16 + gid;
        const int r1 = r0 + 8;
#pragma unroll
        for (int na = 0; na < 8; na++){
            const int c = n0 + wn + na*8 + 2*tig;
            const float2 bb = *(const float2*)&bias[c];
            float v00 = acc[ma][na][0] + bb.x;
            float v01 = acc[ma][na][1] + bb.y;
            float v10 = acc[ma][na][2] + bb.x;
            float v11 = acc[ma][na][3] + bb.y;
            if (RELU){
                v00 = fmaxf(v00,0.f); v01 = fmaxf(v01,0.f);
                v10 = fmaxf(v10,0.f); v11 = fmaxf(v11,0.f);
            }
            if (RES){
                const float2 q0 = *(const float2*)&res[(size_t)r0*N + c];
                const float2 q1 = *(const float2*)&res[(size_t)r1*N + c];
                v00 += q0.x; v01 += q0.y; v10 += q1.x; v11 += q1.y;
            }
            if (OUTH){
                __half* Ch = (__half*)Cv;
                *(__half2*)&Ch[(size_t)r0*N + c] = __floats2half2_rn(v00, v01);
                *(__half2*)&Ch[(size_t)r1*N + c] = __floats2half2_rn(v10, v11);
            } else {
                float* Cf = (float*)Cv;
                float2 o0; o0.x=v00; o0.y=v01;
                float2 o1; o1.x=v10; o1.y=v11;
                *(float2*)&Cf[(size_t)r0*N + c] = o0;
                *(float2*)&Cf[(size_t)r1*N + c] = o1;
            }
        }
    }
}

template<bool RELU, bool RES, bool OUTH>
__global__ __launch_bounds__(256,2)
void gemm_h(const __half* __restrict__ A, const __half* __restrict__ W,
            const float* __restrict__ bias, const float* __restrict__ res,
            void* __restrict__ Cv, int N, int K)
{
    gemm_body<RELU,RES,OUTH>(A, W, bias, res, Cv, N, K,
                             blockIdx.y*128, blockIdx.x*128);
}

// cross-attn fused: blocks 0..7 -> Q proj (N=1024), blocks 8..23 -> KV proj (N=2048)
__global__ __launch_bounds__(256,2)
void gemm_dual(const __half* __restrict__ A0, const __half* __restrict__ W0,
               const float* __restrict__ b0, __half* __restrict__ C0,
               const __half* __restrict__ A1, const __half* __restrict__ W1,
               const float* __restrict__ b1, __half* __restrict__ C1)
{
    const int bx = blockIdx.x;
    const __half* A; const __half* W; const float* bias; __half* C; int N, n0;
    if (bx < 8){ A = A0; W = W0; bias = b0; C = C0; N = 1024; n0 = bx*128; }
    else       { A = A1; W = W1; bias = b1; C = C1; N = 2048; n0 = (bx-8)*128; }
    gemm_body<false,false,true>(A, W, bias, nullptr, C, N, 1024,
                                blockIdx.y*128, n0);
}

// ---------------- Flash attention fp16, pre-scaled Q, log2-domain softmax ----
#define ATP 72
#define KVB (64*ATP)
#define ATTN_SMEM ((128*ATP + 4*KVB)*2)
template<bool CAUSAL>
__global__ __launch_bounds__(256,2)
void attn_h(const __half* __restrict__ Qg, const __half* __restrict__ Kg,
            const __half* __restrict__ Vg, __half* __restrict__ Og,
            int ldq, int ldkv)
{
    extern __shared__ __half smh[];
    __half* Qs = smh;
    __half* Ks = Qs + 128*ATP;
    __half* Vs = Ks + 2*KVB;

    const int tid  = threadIdx.x;
    const int lane = tid & 31;
    const int wid  = tid >> 5;
    const int gid  = lane >> 2;
    const int tig  = lane & 3;
    const int wm   = wid * 16;
    const int qb = CAUSAL ? ((int)gridDim.x - 1 - (int)blockIdx.x) : (int)blockIdx.x;
    const int h = blockIdx.y, b = blockIdx.z;
    const size_t baseq = (size_t)b*TSEQ*ldq  + (size_t)h*64;
    const size_t basek = (size_t)b*TSEQ*ldkv + (size_t)h*64;
    const size_t baseo = (size_t)b*TSEQ*EDIM + (size_t)h*64;

    const uint32_t qsb = (uint32_t)__cvta_generic_to_shared(Qs);
    const uint32_t ksb = (uint32_t)__cvta_generic_to_shared(Ks);
    const uint32_t vsb = (uint32_t)__cvta_generic_to_shared(Vs);

#pragma unroll
    for (int i = 0; i < 4; i++){
        int idx = tid + 256*i;
        int r = idx>>3, c = (idx&7)*8;
        cpa16(qsb + (uint32_t)((r*ATP + c)*2), Qg + baseq + (size_t)(qb*128 + r)*ldq + c);
    }
    CP_COMMIT();
#define LOADKV(b_, kt_) do{                                                   \
        _Pragma("unroll")                                                     \
        for (int i = 0; i < 2; i++){                                          \
            int idx = tid + 256*i;                                            \
            int r = idx>>3, c = (idx&7)*8;                                    \
            size_t go = basek + (size_t)((kt_)*64 + r)*ldkv + c;              \
            uint32_t so = (uint32_t)(((b_)*KVB + r*ATP + c)*2);               \
            cpa16(ksb + so, Kg + go);                                         \
            cpa16(vsb + so, Vg + go);                                         \
        }                                                                     \
        CP_COMMIT();                                                          \
    }while(0)
    LOADKV(0, 0);
    CP_WAIT(1);
    __syncthreads();

    const int q_r = wm + (lane&7) + ((lane>>3)&1)*8;
    const int q_k = ((lane>>4)&1)*8;
    uint32_t qf[4][4];
#pragma unroll
    for (int kc = 0; kc < 4; kc++)
        ldsm4(qf[kc], qsb + (uint32_t)((q_r*ATP + q_k + kc*16)*2));

    const int k_r = (lane&7);
    const int k_c = (lane>>3)*8;
    const int v_r = (lane&7) + ((lane>>3)&1)*8;
    const int v_n = ((lane>>4)&1)*8;

    float oacc[8][4];
#pragma unroll
    for (int i=0;i<8;i++)
#pragma unroll
        for (int j=0;j<4;j++) oacc[i][j]=0.f;
    float m0=-1e30f, m1=-1e30f, l0=0.f, l1=0.f;

    const int nkt = CAUSAL ? (2*qb + 2) : (TSEQ/64);
    const int gr0 = qb*128 + wm + gid;
    const int gr1 = gr0 + 8;

    for (int kt = 0; kt < nkt; ++kt){
        CP_WAIT(0);
        __syncthreads();
        const int buf = kt & 1;
        if (kt + 1 < nkt) LOADKV(buf^1, kt+1);
        const uint32_t ksb_b = ksb + (uint32_t)(buf*KVB*2);
        const uint32_t vsb_b = vsb + (uint32_t)(buf*KVB*2);

        // S (already log2-domain: Q pre-scaled by 0.125*log2e at projection)
        float sa[8][4];
#pragma unroll
        for (int na=0;na<8;na++)
#pragma unroll
            for (int e=0;e<4;e++) sa[na][e]=0.f;
#pragma unroll
        for (int na = 0; na < 8; na++){
#pragma unroll
            for (int kq = 0; kq < 2; kq++){
                uint32_t kf[4];
                ldsm4(kf, ksb_b + (uint32_t)(((na*8 + k_r)*ATP + kq*32 + k_c)*2));
                mma_f16(sa[na], qf[2*kq  ], kf[0], kf[1]);
                mma_f16(sa[na], qf[2*kq+1], kf[2], kf[3]);
            }
        }
        if (CAUSAL && kt >= 2*qb){
#pragma unroll
            for (int na = 0; na < 8; na++){
                const int c0 = kt*64 + na*8 + 2*tig;
#pragma unroll
                for (int e = 0; e < 4; e++){
                    const int col = c0 + (e&1);
                    const int row = (e<2) ? gr0 : gr1;
                    if (col > row) sa[na][e] = -1e30f;
                }
            }
        }
        float mx0=-1e30f, mx1=-1e30f;
#pragma unroll
        for (int na=0;na<8;na++){
            mx0 = fmaxf(mx0, fmaxf(sa[na][0], sa[na][1]));
            mx1 = fmaxf(mx1, fmaxf(sa[na][2], sa[na][3]));
        }
        mx0 = fmaxf(mx0, __shfl_xor_sync(0xffffffffu, mx0, 1));
        mx0 = fmaxf(mx0, __shfl_xor_sync(0xffffffffu, mx0, 2));
        mx1 = fmaxf(mx1, __shfl_xor_sync(0xffffffffu, mx1, 1));
        mx1 = fmaxf(mx1, __shfl_xor_sync(0xffffffffu, mx1, 2));
        const float mn0 = fmaxf(m0, mx0);
        const float mn1 = fmaxf(m1, mx1);
        const float al0 = exp2f(m0 - mn0);
        const float al1 = exp2f(m1 - mn1);
        m0 = mn0; m1 = mn1;
        uint32_t pf[4][4];
#pragma unroll
        for (int kc = 0; kc < 4; kc++){
            pf[kc][0] = pexp2(sa[2*kc  ][0]-mn0, sa[2*kc  ][1]-mn0);
            pf[kc][1] = pexp2(sa[2*kc  ][2]-mn1, sa[2*kc  ][3]-mn1);
            pf[kc][2] = pexp2(sa[2*kc+1][0]-mn0, sa[2*kc+1][1]-mn0);
            pf[kc][3] = pexp2(sa[2*kc+1][2]-mn1, sa[2*kc+1][3]-mn1);
        }
        float lacc[4] = {0.f, 0.f, 0.f, 0.f};
#pragma unroll
        for (int kc = 0; kc < 4; kc++)
            mma_f16(lacc, pf[kc], HONES, HONES);
        l0 = l0*al0 + lacc[0];
        l1 = l1*al1 + lacc[2];
#pragma unroll
        for (int na=0;na<8;na++){
            oacc[na][0]*=al0; oacc[na][1]*=al0;
            oacc[na][2]*=al1; oacc[na][3]*=al1;
        }
#pragma unroll
        for (int kc = 0; kc < 4; kc++){
#pragma unroll
            for (int np = 0; np < 4; np++){
                uint32_t vf[4];
                ldsm4t(vf, vsb_b + (uint32_t)(((kc*16 + v_r)*ATP + v_n + np*16)*2));
                mma_f16(oacc[2*np  ], pf[kc], vf[0], vf[1]);
                mma_f16(oacc[2*np+1], pf[kc], vf[2], vf[3]);
            }
        }
    }
#undef LOADKV

    const float li0 = 1.f / l0;
    const float li1 = 1.f / l1;
#pragma unroll
    for (int na = 0; na < 8; na++){
        const int c = na*8 + 2*tig;
        *(__half2*)&Og[baseo + (size_t)gr0*EDIM + c] =
            __floats2half2_rn(oacc[na][0]*li0, oacc[na][1]*li0);
        *(__half2*)&Og[baseo + (size_t)gr1*EDIM + c] =
            __floats2half2_rn(oacc[na][2]*li1, oacc[na][3]*li1);
    }
}

// ---------------- launch ----------------
extern "C" void kernel_launch(void* const* d_in, const int* in_sizes, int n_in,
                              void* d_out, int out_size)
{
    const float* x     = (const float*)d_in[0];
    const float* enc   = (const float*)d_in[1];
    const float* sa_wq = (const float*)d_in[3];  const float* sa_bq = (const float*)d_in[4];
    const float* sa_wk = (const float*)d_in[5];  const float* sa_bk = (const float*)d_in[6];
    const float* sa_wv = (const float*)d_in[7];  const float* sa_bv = (const float*)d_in[8];
    const float* sa_wo = (const float*)d_in[9];  const float* sa_bo = (const float*)d_in[10];
    const float* ca_wq = (const float*)d_in[11]; const float* ca_bq = (const float*)d_in[12];
    const float* ca_wk = (const float*)d_in[13]; const float* ca_bk = (const float*)d_in[14];
    const float* ca_wv = (const float*)d_in[15]; const float* ca_bv = (const float*)d_in[16];
    const float* ca_wo = (const float*)d_in[17]; const float* ca_bo = (const float*)d_in[18];
    const float* ff_w1 = (const float*)d_in[19]; const float* ff_b1 = (const float*)d_in[20];
    const float* ff_w2 = (const float*)d_in[21]; const float* ff_b2 = (const float*)d_in[22];
    const float* ln1g  = (const float*)d_in[23]; const float* ln1b  = (const float*)d_in[24];
    const float* ln2g  = (const float*)d_in[25]; const float* ln2b  = (const float*)d_in[26];
    const float* ln3g  = (const float*)d_in[27]; const float* ln3b  = (const float*)d_in[28];
    float* out = (float*)d_out;

    __half *wh, *ench, *hh, *qkvh, *qh, *aoh, *ffh;
    float *x1, *x2, *bqkv, *bkv, *bqc;
    cudaGetSymbolAddress((void**)&wh,   g_wh);
    cudaGetSymbolAddress((void**)&ench, g_ench);
    cudaGetSymbolAddress((void**)&hh,   g_hh);
    cudaGetSymbolAddress((void**)&qkvh, g_qkvh);
    cudaGetSymbolAddress((void**)&qh,   g_qh);
    cudaGetSymbolAddress((void**)&aoh,  g_aoh);
    cudaGetSymbolAddress((void**)&ffh,  g_ffh);
    cudaGetSymbolAddress((void**)&x1,   g_x1);
    cudaGetSymbolAddress((void**)&x2,   g_x2);
    cudaGetSymbolAddress((void**)&bqkv, g_bqkv);
    cudaGetSymbolAddress((void**)&bkv,  g_bkv);
    cudaGetSymbolAddress((void**)&bqc,  g_bqc);

    cudaFuncSetAttribute(attn_h<true>,  cudaFuncAttributeMaxDynamicSharedMemorySize, ATTN_SMEM);
    cudaFuncSetAttribute(attn_h<false>, cudaFuncAttributeMaxDynamicSharedMemorySize, ATTN_SMEM);
    cudaFuncSetAttribute(gemm_h<false,false,true >, cudaFuncAttributeMaxDynamicSharedMemorySize, GEMM_SMEM);
    cudaFuncSetAttribute(gemm_h<false,true ,false>, cudaFuncAttributeMaxDynamicSharedMemorySize, GEMM_SMEM);
    cudaFuncSetAttribute(gemm_h<true ,false,true >, cudaFuncAttributeMaxDynamicSharedMemorySize, GEMM_SMEM);
    cudaFuncSetAttribute(gemm_dual, cudaFuncAttributeMaxDynamicSharedMemorySize, GEMM_SMEM);

    const long cvt_total = 8L*SEGP + 3L*MEGA + 1536;
    cvt_all<<<(unsigned)((cvt_total + 255)/256), 256>>>(
        sa_wq, sa_wk, sa_wv, sa_wo, ca_wq, ca_wk, ca_wv, ca_wo,
        ff_w1, ff_w2, enc, sa_bq, sa_bk, sa_bv, ca_bq, ca_bk, ca_bv,
        wh, ench, bqkv, bkv, bqc);

    const dim3 thr(256);
    const dim3 gQKV(3072/128, NTOK/128);
    const dim3 gP  (EDIM/128, NTOK/128);
    const dim3 gF1 (FFD/128,  NTOK/128);
    const dim3 gD  (24, NTOK/128);
    const dim3 gA  (TSEQ/128, 16, 2);

    // ---- self attention ----
    ln_kernel<<<NTOK, 256>>>(x, ln1g, ln1b, hh);
    gemm_h<false,false,true ><<<gQKV, thr, GEMM_SMEM>>>(hh, wh, bqkv, nullptr, qkvh, 3072, 1024);
    attn_h<true><<<gA, thr, ATTN_SMEM>>>(qkvh, qkvh+1024, qkvh+2048, aoh, 3072, 3072);
    gemm_h<false,true ,false><<<gP, thr, GEMM_SMEM>>>(aoh, wh+(size_t)3*MEGA, sa_bo, x, x1, EDIM, EDIM);

    // ---- cross attention (Q proj + KV proj fused into one launch) ----
    ln_kernel<<<NTOK, 256>>>(x1, ln2g, ln2b, hh);
    gemm_dual<<<gD, thr, GEMM_SMEM>>>(hh, wh+(size_t)4*MEGA, bqc, qh,
                                      ench, wh+(size_t)5*MEGA, bkv, qkvh);
    attn_h<false><<<gA, thr, ATTN_SMEM>>>(qh, qkvh, qkvh+1024, aoh, 1024, 2048);
    gemm_h<false,true ,false><<<gP, thr, GEMM_SMEM>>>(aoh, wh+(size_t)7*MEGA, ca_bo, x1, x2, EDIM, EDIM);

    // ---- feed-forward ----
    ln_kernel<<<NTOK, 256>>>(x2, ln3g, ln3b, hh);
    gemm_h<true ,false,true ><<<gF1, thr, GEMM_SMEM>>>(hh,  wh+(size_t)8*MEGA,  ff_b1, nullptr, ffh, FFD, 1024);
    gemm_h<false,true ,false><<<gP, thr, GEMM_SMEM>>>(ffh, wh+(size_t)12*MEGA, ff_b2, x2, out, EDIM, FFD);
}